// round 12
// baseline (speedup 1.0000x reference)
#include <cuda_runtime.h>
#include <cuda_bf16.h>
#include <math.h>
#include <float.h>
#include <stdint.h>

// Problem dims (fixed)
#define BATCH 2
#define SEQ   2048
#define DMODEL 1024
#define NHEAD 16
#define HDIM  64
#define FFN   4096
#define MTOK  (BATCH*SEQ)          // 4096 token rows
#define SEGSZ ((size_t)MTOK*DMODEL)

typedef __nv_bfloat16 bf16;

// ---------------- scratch (allocation-free: __device__ globals) ----------------
__device__ float g_res1[MTOK*DMODEL];

__device__ bf16 g_ln1_hi[MTOK*DMODEL], g_ln1_lo[MTOK*DMODEL];
// fused QKV activations: [Q(pre-scaled 1/8) tok-major | K tok-major | V head-transposed]
__device__ bf16 g_qkv_hi[3*MTOK*DMODEL], g_qkv_lo[3*MTOK*DMODEL];
__device__ bf16 g_ctx_hi[MTOK*DMODEL], g_ctx_lo[MTOK*DMODEL];
__device__ bf16 g_ln2_hi[MTOK*DMODEL], g_ln2_lo[MTOK*DMODEL];
__device__ bf16 g_h1_hi [MTOK*FFN],    g_h1_lo [MTOK*FFN];

__device__ bf16 g_wqkvT_hi[3*DMODEL*DMODEL], g_wqkvT_lo[3*DMODEL*DMODEL];
__device__ bf16 g_woT_hi[DMODEL*DMODEL],     g_woT_lo[DMODEL*DMODEL];
__device__ bf16 g_w1T_hi[DMODEL*FFN],        g_w1T_lo[DMODEL*FFN];
__device__ bf16 g_w2T_hi[FFN*DMODEL],        g_w2T_lo[FFN*DMODEL];

// ---------------- PTX helpers (baseline compute_103-safe: sm_80-era ops only) ----
__device__ __forceinline__ uint32_t smem_u32(const void* p) {
    uint32_t a;
    asm("{ .reg .u64 t; cvta.to.shared.u64 t, %1; cvt.u32.u64 %0, t; }" : "=r"(a) : "l"(p));
    return a;
}
__device__ __forceinline__ void cpa16(uint32_t dst, const void* src) {
    asm volatile("cp.async.cg.shared.global [%0], [%1], 16;" :: "r"(dst), "l"(src));
}
__device__ __forceinline__ void cpa_commit() { asm volatile("cp.async.commit_group;"); }
__device__ __forceinline__ void cpa_wait2()  { asm volatile("cp.async.wait_group 2;" ::: "memory"); }
__device__ __forceinline__ void cpa_wait1()  { asm volatile("cp.async.wait_group 1;" ::: "memory"); }
__device__ __forceinline__ void cpa_wait0()  { asm volatile("cp.async.wait_group 0;" ::: "memory"); }

#define LDSM4(r, a) \
    asm volatile("ldmatrix.sync.aligned.m8n8.x4.shared.b16 {%0,%1,%2,%3}, [%4];" \
        : "=r"((r)[0]), "=r"((r)[1]), "=r"((r)[2]), "=r"((r)[3]) : "r"(a))

#define MMA_BF16(d, a, b0, b1) \
    asm volatile("mma.sync.aligned.m16n8k16.row.col.f32.bf16.bf16.f32 " \
        "{%0,%1,%2,%3}, {%4,%5,%6,%7}, {%8,%9}, {%0,%1,%2,%3};" \
        : "+f"((d)[0]), "+f"((d)[1]), "+f"((d)[2]), "+f"((d)[3]) \
        : "r"((a)[0]), "r"((a)[1]), "r"((a)[2]), "r"((a)[3]), "r"(b0), "r"(b1))

__device__ __forceinline__ float gelu_tanh(float x) {
    const float c = 0.7978845608028654f;
    float t = c * (x + 0.044715f * x * x * x);
    return 0.5f * x * (1.0f + tanhf(t));
}
__device__ __forceinline__ void split_hl(float v, bf16& h, bf16& l) {
    h = __float2bfloat16(v);
    l = __float2bfloat16(v - __bfloat162float(h));
}
__device__ __forceinline__ uint32_t pk2(float x, float y) {
    __nv_bfloat162 t;
    t.x = __float2bfloat16(x);
    t.y = __float2bfloat16(y);
    return *(uint32_t*)&t;
}

// ---------------- LayerNorm -> hi/lo bf16 (torch var ddof=1) ----------------
__global__ __launch_bounds__(256)
void ln_hl_kernel(const float* __restrict__ x, const float* __restrict__ sc,
                  const float* __restrict__ sh, bf16* __restrict__ ohi, bf16* __restrict__ olo)
{
    int row = blockIdx.x;
    int tid = threadIdx.x;
    const float4 a = *(const float4*)&x[(size_t)row * DMODEL + tid * 4];

    float s = a.x + a.y + a.z + a.w;
    float q = a.x*a.x + a.y*a.y + a.z*a.z + a.w*a.w;
    #pragma unroll
    for (int off = 16; off > 0; off >>= 1) {
        s += __shfl_xor_sync(0xFFFFFFFFu, s, off);
        q += __shfl_xor_sync(0xFFFFFFFFu, q, off);
    }
    __shared__ float reds[8], redq[8], stats[2];
    int wid = tid >> 5, lane = tid & 31;
    if (lane == 0) { reds[wid] = s; redq[wid] = q; }
    __syncthreads();
    if (tid == 0) {
        float S = 0.f, Q = 0.f;
        #pragma unroll
        for (int i = 0; i < 8; i++) { S += reds[i]; Q += redq[i]; }
        float mean = S * (1.0f / DMODEL);
        float var  = (Q - S * mean) * (1.0f / (DMODEL - 1));
        stats[0] = mean;
        stats[1] = rsqrtf(var + 1e-5f);
    }
    __syncthreads();
    float mean = stats[0], rstd = stats[1];
    const float4 scv = *(const float4*)&sc[tid * 4];
    const float4 shv = *(const float4*)&sh[tid * 4];
    float o[4];
    o[0] = (a.x - mean) * rstd * scv.x + shv.x;
    o[1] = (a.y - mean) * rstd * scv.y + shv.y;
    o[2] = (a.z - mean) * rstd * scv.z + shv.z;
    o[3] = (a.w - mean) * rstd * scv.w + shv.w;

    union { bf16 b[4]; uint2 u; } uh, ul;
    #pragma unroll
    for (int i = 0; i < 4; i++) split_hl(o[i], uh.b[i], ul.b[i]);
    size_t idx = (size_t)row * DMODEL + tid * 4;
    *(uint2*)&ohi[idx] = uh.u;
    *(uint2*)&olo[idx] = ul.u;
}

// ---------------- weight transpose+convert: W[K,N] f32 -> WT hi/lo bf16 [N,K] ----------------
__global__ __launch_bounds__(256)
void wconvT(const float* __restrict__ W, bf16* __restrict__ ThT, bf16* __restrict__ TlT,
            int K, int N)
{
    __shared__ float t[32][33];
    int tx = threadIdx.x & 31, ty = threadIdx.x >> 5;
    int k0 = blockIdx.y * 32, n0 = blockIdx.x * 32;
    #pragma unroll
    for (int j = 0; j < 4; j++)
        t[ty + j * 8][tx] = W[(size_t)(k0 + ty + j * 8) * N + n0 + tx];
    __syncthreads();
    #pragma unroll
    for (int j = 0; j < 4; j++) {
        int n = n0 + ty + j * 8;
        float v = t[tx][ty + j * 8];
        bf16 h, l; split_hl(v, h, l);
        ThT[(size_t)n * K + k0 + tx] = h;
        TlT[(size_t)n * K + k0 + tx] = l;
    }
}

// batched: wq/wk/wv -> fused qkvT buffer (z=0..2), wo -> woT (z=3); all 1024x1024
__global__ __launch_bounds__(256)
void wconv_qkvo(const float* __restrict__ wq, const float* __restrict__ wk,
                const float* __restrict__ wv, const float* __restrict__ wo,
                bf16* __restrict__ qkvh, bf16* __restrict__ qkvl,
                bf16* __restrict__ woh, bf16* __restrict__ wol)
{
    const int z = blockIdx.z;
    const float* W = (z == 0) ? wq : (z == 1) ? wk : (z == 2) ? wv : wo;
    bf16* Th = (z < 3) ? qkvh + (size_t)z * DMODEL * DMODEL : woh;
    bf16* Tl = (z < 3) ? qkvl + (size_t)z * DMODEL * DMODEL : wol;

    __shared__ float t[32][33];
    int tx = threadIdx.x & 31, ty = threadIdx.x >> 5;
    int k0 = blockIdx.y * 32, n0 = blockIdx.x * 32;
    #pragma unroll
    for (int j = 0; j < 4; j++)
        t[ty + j * 8][tx] = W[(size_t)(k0 + ty + j * 8) * DMODEL + n0 + tx];
    __syncthreads();
    #pragma unroll
    for (int j = 0; j < 4; j++) {
        int n = n0 + ty + j * 8;
        float v = t[tx][ty + j * 8];
        bf16 h, l; split_hl(v, h, l);
        Th[(size_t)n * DMODEL + k0 + tx] = h;
        Tl[(size_t)n * DMODEL + k0 + tx] = l;
    }
}

// ---------------- mma.sync bf16x3 GEMM: C[M,N] = A[M,K] @ B^T (B given as [N,K]) --
// CTA 128x128, BK=32, 256 threads, warp grid 2(M)x4(N), warp tile 64x32.
// 2 CTAs/SM (96 KB smem, <=128 regs). 3-stage cp.async, one barrier per chunk:
//   wait(own chunk-i) -> __syncthreads -> prefetch i+2 into stage (i-1)%3 -> compute i.
// smem tile: 128 rows x 64 B; swizzle off(row,c16) = row*64 + ((c16 ^ ((row>>1)&3))<<4)
//   -> each ldmatrix 8-addr phase hits 8 distinct 16B slots mod 128 (conflict-free).
// Register-lean passes: load ah/bh/bl -> hh,hl passes -> load al (ah dead) -> lh pass.
// EPI: 2 = +bias,gelu -> hi/lo bf16; 3 = +bias +res -> fp32;
//      5 = fused QKV routing (seg0 Q*0.125, seg1 K tok-major; seg2 V head-transposed)
#define TILE_B32 8192
#define STAGE_B32 (4*TILE_B32)           // 32768
#define GEMM_SMEM (3*STAGE_B32)          // 98304

#define SWZ32(row, c16) ((row) * 64 + ((((c16) ^ (((row) >> 1) & 3))) << 4))

template<int EPI>
__global__ __launch_bounds__(256, 2)
void gemm_mma(const bf16* __restrict__ Ahi, const bf16* __restrict__ Alo,
              const bf16* __restrict__ Bhi, const bf16* __restrict__ Blo,
              const float* __restrict__ bias, const float* __restrict__ res,
              float* __restrict__ Cf, bf16* __restrict__ Chi, bf16* __restrict__ Clo,
              int M, int N, int K)
{
    extern __shared__ char smem[];
    const uint32_t sbase = smem_u32(smem);
    const int tid  = threadIdx.x;
    const int wid  = tid >> 5, lane = tid & 31;
    const int m0 = blockIdx.y * 128, n0 = blockIdx.x * 128;
    const int wm = (wid & 1) * 64, wn = (wid >> 1) * 32;

    const bf16* srcs[4];
    srcs[0] = Ahi + (size_t)m0 * K;
    srcs[1] = Alo + (size_t)m0 * K;
    srcs[2] = Bhi + (size_t)n0 * K;
    srcs[3] = Blo + (size_t)n0 * K;

    float acc[4][4][4];
    #pragma unroll
    for (int a = 0; a < 4; a++)
        #pragma unroll
        for (int b = 0; b < 4; b++)
            #pragma unroll
            for (int c = 0; c < 4; c++) acc[a][b][c] = 0.f;

    const int NC = K >> 5;

    auto load_stage = [&](int chunk, int stage) {
        const int k0 = chunk << 5;
        const uint32_t base = sbase + stage * STAGE_B32;
        #pragma unroll
        for (int j = 0; j < 8; j++) {
            const int tile  = j >> 1;
            const int inner = ((j & 1) << 8) + tid;     // 0..511
            const int row   = inner >> 2;               // 0..127
            const int c16   = inner & 3;
            uint32_t dst = base + tile * TILE_B32 + SWZ32(row, c16);
            cpa16(dst, srcs[tile] + (size_t)row * K + k0 + c16 * 8);
        }
        cpa_commit();
    };

    load_stage(0, 0);
    load_stage(1, 1);

    for (int i = 0; i < NC; i++) {
        if (i + 1 < NC) cpa_wait1(); else cpa_wait0();   // own chunk-i group done
        __syncthreads();                                 // publish; fence prev reads
        if (i + 2 < NC) load_stage(i + 2, (i + 2) % 3);  // writes stage (i-1)%3: safe
        const uint32_t tb = sbase + (i % 3) * STAGE_B32;

        #pragma unroll
        for (int ks = 0; ks < 2; ks++) {
            uint32_t af[4][4], bh[2][4], bl[2][4];
            // A-hi fragments
            #pragma unroll
            for (int mt = 0; mt < 4; mt++) {
                int row = wm + mt * 16 + (lane & 15);
                int kg  = ks * 2 + (lane >> 4);
                LDSM4(af[mt], tb + SWZ32(row, kg));
            }
            // B-hi / B-lo fragments
            #pragma unroll
            for (int bt = 0; bt < 2; bt++) {
                int row = wn + bt * 16 + ((lane >> 4) << 3) + (lane & 7);
                int kg  = ks * 2 + ((lane >> 3) & 1);
                uint32_t off = SWZ32(row, kg);
                LDSM4(bh[bt], tb + 2 * TILE_B32 + off);
                LDSM4(bl[bt], tb + 3 * TILE_B32 + off);
            }
            // pass hh
            #pragma unroll
            for (int mt = 0; mt < 4; mt++)
                #pragma unroll
                for (int nt = 0; nt < 4; nt++)
                    MMA_BF16(acc[mt][nt], af[mt],
                             bh[nt >> 1][(nt & 1) * 2], bh[nt >> 1][(nt & 1) * 2 + 1]);
            // pass hl
            #pragma unroll
            for (int mt = 0; mt < 4; mt++)
                #pragma unroll
                for (int nt = 0; nt < 4; nt++)
                    MMA_BF16(acc[mt][nt], af[mt],
                             bl[nt >> 1][(nt & 1) * 2], bl[nt >> 1][(nt & 1) * 2 + 1]);
            // A-lo fragments (reuse af)
            #pragma unroll
            for (int mt = 0; mt < 4; mt++) {
                int row = wm + mt * 16 + (lane & 15);
                int kg  = ks * 2 + (lane >> 4);
                LDSM4(af[mt], tb + TILE_B32 + SWZ32(row, kg));
            }
            // pass lh
            #pragma unroll
            for (int mt = 0; mt < 4; mt++)
                #pragma unroll
                for (int nt = 0; nt < 4; nt++)
                    MMA_BF16(acc[mt][nt], af[mt],
                             bh[nt >> 1][(nt & 1) * 2], bh[nt >> 1][(nt & 1) * 2 + 1]);
        }
    }

    // ---- epilogue (fragment: rows g, g+8; cols 2t, 2t+1) ----
    const int g = lane >> 2, t = lane & 3;
    #pragma unroll
    for (int mt = 0; mt < 4; mt++) {
        #pragma unroll
        for (int nt = 0; nt < 4; nt++) {
            const int gr0 = m0 + wm + mt * 16 + g;
            const int gr1 = gr0 + 8;
            const int gc  = n0 + wn + nt * 8 + 2 * t;
            float v00 = acc[mt][nt][0], v01 = acc[mt][nt][1];
            float v10 = acc[mt][nt][2], v11 = acc[mt][nt][3];
            if (EPI == 3) {
                const float2 bv  = *(const float2*)&bias[gc];
                const float2 r0v = *(const float2*)&res[(size_t)gr0 * N + gc];
                const float2 r1v = *(const float2*)&res[(size_t)gr1 * N + gc];
                *(float2*)&Cf[(size_t)gr0 * N + gc] =
                    make_float2(v00 + bv.x + r0v.x, v01 + bv.y + r0v.y);
                *(float2*)&Cf[(size_t)gr1 * N + gc] =
                    make_float2(v10 + bv.x + r1v.x, v11 + bv.y + r1v.y);
            } else if (EPI == 2) {
                const float2 bv = *(const float2*)&bias[gc];
                float x00 = gelu_tanh(v00 + bv.x), x01 = gelu_tanh(v01 + bv.y);
                float x10 = gelu_tanh(v10 + bv.x), x11 = gelu_tanh(v11 + bv.y);
                __nv_bfloat162 h0, l0, h1, l1;
                split_hl(x00, h0.x, l0.x); split_hl(x01, h0.y, l0.y);
                split_hl(x10, h1.x, l1.x); split_hl(x11, h1.y, l1.y);
                *(__nv_bfloat162*)&Chi[(size_t)gr0 * N + gc] = h0;
                *(__nv_bfloat162*)&Clo[(size_t)gr0 * N + gc] = l0;
                *(__nv_bfloat162*)&Chi[(size_t)gr1 * N + gc] = h1;
                *(__nv_bfloat162*)&Clo[(size_t)gr1 * N + gc] = l1;
            } else { // EPI == 5: fused QKV
                const int seg = gc >> 10;       // constant per CTA
                const int col = gc & 1023;
                if (seg == 0) { v00 *= 0.125f; v01 *= 0.125f; v10 *= 0.125f; v11 *= 0.125f; }
                if (seg < 2) {
                    const size_t base = (size_t)seg * SEGSZ;
                    __nv_bfloat162 h0, l0, h1, l1;
                    split_hl(v00, h0.x, l0.x); split_hl(v01, h0.y, l0.y);
                    split_hl(v10, h1.x, l1.x); split_hl(v11, h1.y, l1.y);
                    *(__nv_bfloat162*)&Chi[base + (size_t)gr0 * DMODEL + col] = h0;
                    *(__nv_bfloat162*)&Clo[base + (size_t)gr0 * DMODEL + col] = l0;
                    *(__nv_bfloat162*)&Chi[base + (size_t)gr1 * DMODEL + col] = h1;
                    *(__nv_bfloat162*)&Clo[base + (size_t)gr1 * DMODEL + col] = l1;
                } else {    // V head-transposed: [b*16+h][d][s]
                    #pragma unroll
                    for (int e = 0; e < 4; e++) {
                        int gr = (e < 2) ? gr0 : gr1;
                        int cc = col + (e & 1);
                        float v = (e == 0) ? v00 : (e == 1) ? v01 : (e == 2) ? v10 : v11;
                        int b = gr >> 11, s = gr & 2047;
                        int h = cc >> 6, d = cc & 63;
                        size_t o = 2 * SEGSZ + ((size_t)((b * 16 + h) * 64 + d)) * 2048 + s;
                        bf16 hh, ll; split_hl(v, hh, ll);
                        Chi[o] = hh;
                        Clo[o] = ll;
                    }
                }
            }
        }
    }
}

// ---------------- mma.sync flash attention (bf16x3, causal) -> ctx hi/lo ----------
// CTA: 128 q-rows x one (b,h). 256 threads = 8 warps x 16 rows. KV tile = 64 keys.
// Q is pre-scaled by 1/8 at the QKV epilogue. (Unchanged from R11.)
#define ATT_SMEM (32768 + 2*32768)

__global__ __launch_bounds__(256, 1)
void attn_mma(const bf16* __restrict__ qhi, const bf16* __restrict__ qlo,
              const bf16* __restrict__ khi, const bf16* __restrict__ klo,
              const bf16* __restrict__ vthi, const bf16* __restrict__ vtlo,
              bf16* __restrict__ chi, bf16* __restrict__ clo)
{
    extern __shared__ char smem[];
    const uint32_t sbase = smem_u32(smem);
    const int tid  = threadIdx.x;
    const int wid  = tid >> 5, lane = tid & 31;
    const int g = lane >> 2, t = lane & 3;
    const int bh = blockIdx.y;
    const int b = bh >> 4, h = bh & 15;
    const int m0 = (gridDim.x - 1 - blockIdx.x) * 128;   // longest blocks first
    const int nit = m0 / 64 + 2;

    // ---- load Q tile (128 rows, hi/lo) ----
    {
        const bf16* qs[2] = { qhi + ((size_t)(b * SEQ + m0)) * DMODEL + h * 64,
                              qlo + ((size_t)(b * SEQ + m0)) * DMODEL + h * 64 };
        #pragma unroll
        for (int tl = 0; tl < 2; tl++)
            #pragma unroll
            for (int j = 0; j < 4; j++) {
                int cid = j * 256 + tid;
                int row = cid >> 3, c = cid & 7;
                cpa16(sbase + tl * 16384 + row * 128 + ((c ^ (row & 7)) << 4),
                      qs[tl] + (size_t)row * DMODEL + c * 8);
            }
        cpa_commit();
    }

    auto load_kv = [&](int it, int stage) {
        const int n0 = it * 64;
        const uint32_t base = sbase + 32768 + stage * 32768;
        const bf16* ks_[2] = { khi + ((size_t)(b * SEQ + n0)) * DMODEL + h * 64,
                               klo + ((size_t)(b * SEQ + n0)) * DMODEL + h * 64 };
        const bf16* vs_[2] = { vthi + ((size_t)(bh * 64)) * 2048 + n0,
                               vtlo + ((size_t)(bh * 64)) * 2048 + n0 };
        #pragma unroll
        for (int tl = 0; tl < 2; tl++)
            #pragma unroll
            for (int j = 0; j < 2; j++) {
                int cid = j * 256 + tid;
                int row = cid >> 3, c = cid & 7;
                uint32_t sw = row * 128 + ((c ^ (row & 7)) << 4);
                cpa16(base + tl * 8192 + sw,         ks_[tl] + (size_t)row * DMODEL + c * 8);
                cpa16(base + 16384 + tl * 8192 + sw, vs_[tl] + (size_t)row * 2048 + c * 8);
            }
        cpa_commit();
    };

    load_kv(0, 0);
    load_kv(1, 1);

    // Q fragments (constant across iters)
    cpa_wait2();
    __syncthreads();
    uint32_t qh[4][4], ql[4][4];
    #pragma unroll
    for (int ks = 0; ks < 4; ks++) {
        int row = wid * 16 + (lane & 15);
        int kg  = ks * 2 + (lane >> 4);
        uint32_t off = row * 128 + ((kg ^ (row & 7)) << 4);
        LDSM4(qh[ks], sbase + off);
        LDSM4(ql[ks], sbase + 16384 + off);
    }

    float m[2] = { -INFINITY, -INFINITY };
    float l[2] = { 0.f, 0.f };
    float acc_o[8][4];
    #pragma unroll
    for (int i = 0; i < 8; i++)
        #pragma unroll
        for (int c = 0; c < 4; c++) acc_o[i][c] = 0.f;

    const int rowL64 = (wid & 3) * 16 + g;
    const int wdiag  = (wid < 4) ? (nit - 2) : (nit - 1);

    for (int it = 0; it < nit; it++) {
        const int rem = nit - 1 - it;
        if (rem >= 1) cpa_wait1(); else cpa_wait0();
        __syncthreads();
        const uint32_t kb = sbase + 32768 + (it & 1) * 32768;
        const uint32_t vb = kb + 16384;
        const bool active = !(wid < 4 && it == nit - 1);

        if (active) {
            const bool diag = (it == wdiag);

            // ---- S = Q K^T (bf16x3, pass-major) ----
            float s[8][4];
            #pragma unroll
            for (int i = 0; i < 8; i++)
                #pragma unroll
                for (int c = 0; c < 4; c++) s[i][c] = 0.f;

            #pragma unroll
            for (int ks = 0; ks < 4; ks++) {
                uint32_t kh[4][4], kl[4][4];
                #pragma unroll
                for (int bt = 0; bt < 4; bt++) {
                    int row = bt * 16 + ((lane >> 4) << 3) + (lane & 7);
                    int kg  = ks * 2 + ((lane >> 3) & 1);
                    uint32_t off = row * 128 + ((kg ^ (row & 7)) << 4);
                    LDSM4(kh[bt], kb + off);
                    LDSM4(kl[bt], kb + 8192 + off);
                }
                #pragma unroll
                for (int nt = 0; nt < 8; nt++)
                    MMA_BF16(s[nt], qh[ks],
                             kh[nt >> 1][(nt & 1) * 2], kh[nt >> 1][(nt & 1) * 2 + 1]);
                #pragma unroll
                for (int nt = 0; nt < 8; nt++)
                    MMA_BF16(s[nt], qh[ks],
                             kl[nt >> 1][(nt & 1) * 2], kl[nt >> 1][(nt & 1) * 2 + 1]);
                #pragma unroll
                for (int nt = 0; nt < 8; nt++)
                    MMA_BF16(s[nt], ql[ks],
                             kh[nt >> 1][(nt & 1) * 2], kh[nt >> 1][(nt & 1) * 2 + 1]);
            }

            // ---- causal mask + online softmax (Q pre-scaled) ----
            #pragma unroll
            for (int nt = 0; nt < 8; nt++) {
                #pragma unroll
                for (int c = 0; c < 4; c++) {
                    int colL = nt * 8 + 2 * t + (c & 1);
                    int rowL = rowL64 + ((c >> 1) << 3);
                    if (diag && colL > rowL) s[nt][c] = -INFINITY;
                }
            }
            float mx0 = -INFINITY, mx1 = -INFINITY;
            #pragma unroll
            for (int nt = 0; nt < 8; nt++) {
                mx0 = fmaxf(mx0, fmaxf(s[nt][0], s[nt][1]));
                mx1 = fmaxf(mx1, fmaxf(s[nt][2], s[nt][3]));
            }
            mx0 = fmaxf(mx0, __shfl_xor_sync(0xFFFFFFFFu, mx0, 1));
            mx0 = fmaxf(mx0, __shfl_xor_sync(0xFFFFFFFFu, mx0, 2));
            mx1 = fmaxf(mx1, __shfl_xor_sync(0xFFFFFFFFu, mx1, 1));
            mx1 = fmaxf(mx1, __shfl_xor_sync(0xFFFFFFFFu, mx1, 2));
            float mn0 = fmaxf(m[0], mx0), mn1 = fmaxf(m[1], mx1);
            float a0 = __expf(m[0] - mn0), a1 = __expf(m[1] - mn1);
            m[0] = mn0; m[1] = mn1;
            #pragma unroll
            for (int i = 0; i < 8; i++) {
                acc_o[i][0] *= a0; acc_o[i][1] *= a0;
                acc_o[i][2] *= a1; acc_o[i][3] *= a1;
            }
            float sum0 = 0.f, sum1 = 0.f;
            float p[8][4];
            #pragma unroll
            for (int nt = 0; nt < 8; nt++) {
                p[nt][0] = __expf(s[nt][0] - mn0); p[nt][1] = __expf(s[nt][1] - mn0);
                p[nt][2] = __expf(s[nt][2] - mn1); p[nt][3] = __expf(s[nt][3] - mn1);
                sum0 += p[nt][0] + p[nt][1];
                sum1 += p[nt][2] + p[nt][3];
            }
            sum0 += __shfl_xor_sync(0xFFFFFFFFu, sum0, 1);
            sum0 += __shfl_xor_sync(0xFFFFFFFFu, sum0, 2);
            sum1 += __shfl_xor_sync(0xFFFFFFFFu, sum1, 1);
            sum1 += __shfl_xor_sync(0xFFFFFFFFu, sum1, 2);
            l[0] = l[0] * a0 + sum0;
            l[1] = l[1] * a1 + sum1;

            // ---- O += P V (bf16x3, pass-major); P split hi/lo in-register ----
            #pragma unroll
            for (int ks2 = 0; ks2 < 4; ks2++) {
                float ph[8], pl[8];
                #pragma unroll
                for (int e = 0; e < 2; e++) {
                    int nt = 2 * ks2 + e;
                    #pragma unroll
                    for (int c = 0; c < 4; c++) {
                        bf16 hh, ll; split_hl(p[nt][c], hh, ll);
                        ph[e * 4 + c] = __bfloat162float(hh);
                        pl[e * 4 + c] = p[nt][c] - ph[e * 4 + c];
                    }
                }
                uint32_t pah[4], pal[4];
                pah[0] = pk2(ph[0], ph[1]); pah[1] = pk2(ph[2], ph[3]);
                pah[2] = pk2(ph[4], ph[5]); pah[3] = pk2(ph[6], ph[7]);
                pal[0] = pk2(pl[0], pl[1]); pal[1] = pk2(pl[2], pl[3]);
                pal[2] = pk2(pl[4], pl[5]); pal[3] = pk2(pl[6], pl[7]);

                uint32_t vh[4][4], vl[4][4];
                #pragma unroll
                for (int dt = 0; dt < 4; dt++) {
                    int row = dt * 16 + ((lane >> 4) << 3) + (lane & 7);
                    int kg  = ks2 * 2 + ((lane >> 3) & 1);
                    uint32_t off = row * 128 + ((kg ^ (row & 7)) << 4);
                    LDSM4(vh[dt], vb + off);
                    LDSM4(vl[dt], vb + 8192 + off);
                }
                #pragma unroll
                for (int nt = 0; nt < 8; nt++)
                    MMA_BF16(acc_o[nt], pah,
                             vh[nt >> 1][(nt & 1) * 2], vh[nt >> 1][(nt & 1) * 2 + 1]);
                #pragma unroll
                for (int nt = 0; nt < 8; nt++)
                    MMA_BF16(acc_o[nt], pah,
                             vl[nt >> 1][(nt & 1) * 2], vl[nt >> 1][(nt & 1) * 2 + 1]);
                #pragma unroll
                for (int nt = 0; nt < 8; nt++)
                    MMA_BF16(acc_o[nt], pal,
                             vh[nt >> 1][(nt & 1) * 2], vh[nt >> 1][(nt & 1) * 2 + 1]);
            }
        }

        __syncthreads();
        if (it + 2 < nit) load_kv(it + 2, it & 1);
    }

    // ---- epilogue ----
    float inv0 = 1.0f / l[0], inv1 = 1.0f / l[1];
    const size_t gr0 = (size_t)(b * SEQ + m0 + wid * 16 + g) * DMODEL + h * 64;
    const size_t gr1 = gr0 + 8 * DMODEL;
    #pragma unroll
    for (int nt = 0; nt < 8; nt++) {
        int gc = nt * 8 + 2 * t;
        __nv_bfloat162 h0, l0h, h1, l1h;
        split_hl(acc_o[nt][0] * inv0, h0.x, l0h.x);
        split_hl(acc_o[nt][1] * inv0, h0.y, l0h.y);
        split_hl(acc_o[nt][2] * inv1, h1.x, l1h.x);
        split_hl(acc_o[nt][3] * inv1, h1.y, l1h.y);
        *(__nv_bfloat162*)&chi[gr0 + gc] = h0;
        *(__nv_bfloat162*)&clo[gr0 + gc] = l0h;
        *(__nv_bfloat162*)&chi[gr1 + gc] = h1;
        *(__nv_bfloat162*)&clo[gr1 + gc] = l1h;
    }
}

// ---------------- launch ----------------
extern "C" void kernel_launch(void* const* d_in, const int* in_sizes, int n_in,
                              void* d_out, int out_size)
{
    const float* x         = (const float*)d_in[0];
    const float* ln1_scale = (const float*)d_in[1];
    const float* ln1_shift = (const float*)d_in[2];
    const float* wq        = (const float*)d_in[3];
    const float* wk        = (const float*)d_in[4];
    const float* wv        = (const float*)d_in[5];
    const float* w_out     = (const float*)d_in[6];
    const float* b_out     = (const float*)d_in[7];
    const float* ln2_scale = (const float*)d_in[8];
    const float* ln2_shift = (const float*)d_in[9];
    const float* w1        = (const float*)d_in[10];
    const float* b1        = (const float*)d_in[11];
    const float* w2        = (const float*)d_in[12];
    const float* b2        = (const float*)d_in[13];
    float* out = (float*)d_out;

    float *p_res1;
    bf16 *p_ln1h, *p_ln1l, *p_qkvh, *p_qkvl;
    bf16 *p_ctxh, *p_ctxl, *p_ln2h, *p_ln2l, *p_h1h, *p_h1l;
    bf16 *p_wqkvh, *p_wqkvl, *p_woh, *p_wol, *p_w1h, *p_w1l, *p_w2h, *p_w2l;
    cudaGetSymbolAddress((void**)&p_res1,  g_res1);
    cudaGetSymbolAddress((void**)&p_ln1h,  g_ln1_hi);
    cudaGetSymbolAddress((void**)&p_ln1l,  g_ln1_lo);
    cudaGetSymbolAddress((void**)&p_qkvh,  g_qkv_hi);
    cudaGetSymbolAddress((void**)&p_qkvl,  g_qkv_lo);
    cudaGetSymbolAddress((void**)&p_ctxh,  g_ctx_hi);
    cudaGetSymbolAddress((void**)&p_ctxl,  g_ctx_lo);
    cudaGetSymbolAddress((void**)&p_ln2h,  g_ln2_hi);
    cudaGetSymbolAddress((void**)&p_ln2l,  g_ln2_lo);
    cudaGetSymbolAddress((void**)&p_h1h,   g_h1_hi);
    cudaGetSymbolAddress((void**)&p_h1l,   g_h1_lo);
    cudaGetSymbolAddress((void**)&p_wqkvh, g_wqkvT_hi);
    cudaGetSymbolAddress((void**)&p_wqkvl, g_wqkvT_lo);
    cudaGetSymbolAddress((void**)&p_woh,   g_woT_hi);
    cudaGetSymbolAddress((void**)&p_wol,   g_woT_lo);
    cudaGetSymbolAddress((void**)&p_w1h,   g_w1T_hi);
    cudaGetSymbolAddress((void**)&p_w1l,   g_w1T_lo);
    cudaGetSymbolAddress((void**)&p_w2h,   g_w2T_hi);
    cudaGetSymbolAddress((void**)&p_w2l,   g_w2T_lo);

    static bool attr_set = false;
    if (!attr_set) {
        cudaFuncSetAttribute(attn_mma,    cudaFuncAttributeMaxDynamicSharedMemorySize, ATT_SMEM);
        cudaFuncSetAttribute(gemm_mma<2>, cudaFuncAttributeMaxDynamicSharedMemorySize, GEMM_SMEM);
        cudaFuncSetAttribute(gemm_mma<3>, cudaFuncAttributeMaxDynamicSharedMemorySize, GEMM_SMEM);
        cudaFuncSetAttribute(gemm_mma<5>, cudaFuncAttributeMaxDynamicSharedMemorySize, GEMM_SMEM);
        attr_set = true;
    }

    // 0) weight transpose + hi/lo convert
    wconv_qkvo<<<dim3(DMODEL/32, DMODEL/32, 4), 256>>>(wq, wk, wv, w_out,
                                                       p_wqkvh, p_wqkvl, p_woh, p_wol);
    wconvT<<<dim3(FFN/32,    DMODEL/32), 256>>>(w1, p_w1h, p_w1l, DMODEL, FFN);
    wconvT<<<dim3(DMODEL/32, FFN/32),    256>>>(w2, p_w2h, p_w2l, FFN,    DMODEL);

    // 1) LN1 -> hi/lo
    ln_hl_kernel<<<MTOK, 256>>>(x, ln1_scale, ln1_shift, p_ln1h, p_ln1l);

    dim3 gQKV(3*DMODEL/128, MTOK/128);
    dim3 g1024(DMODEL/128,  MTOK/128);
    dim3 g4096(FFN/128,     MTOK/128);

    // 2) fused QKV projection -> hi/lo bf16 (Q pre-scaled 1/8; V head-transposed)
    gemm_mma<5><<<gQKV, 256, GEMM_SMEM>>>(p_ln1h, p_ln1l, p_wqkvh, p_wqkvl,
                                          nullptr, nullptr, nullptr, p_qkvh, p_qkvl,
                                          MTOK, 3*DMODEL, DMODEL);

    // 3) attention (tensor core) -> ctx hi/lo
    dim3 gAttn(SEQ/128, BATCH*NHEAD);
    attn_mma<<<gAttn, 256, ATT_SMEM>>>(p_qkvh,            p_qkvl,
                                       p_qkvh + SEGSZ,    p_qkvl + SEGSZ,
                                       p_qkvh + 2*SEGSZ,  p_qkvl + 2*SEGSZ,
                                       p_ctxh, p_ctxl);

    // 4) out projection + bias + residual(x) -> res1 (fp32)
    gemm_mma<3><<<g1024, 256, GEMM_SMEM>>>(p_ctxh, p_ctxl, p_woh, p_wol,
                                           b_out, x, p_res1, nullptr, nullptr,
                                           MTOK, DMODEL, DMODEL);

    // 5) LN2 -> hi/lo
    ln_hl_kernel<<<MTOK, 256>>>(p_res1, ln2_scale, ln2_shift, p_ln2h, p_ln2l);

    // 6) FFN1 + bias + gelu -> h1 hi/lo
    gemm_mma<2><<<g4096, 256, GEMM_SMEM>>>(p_ln2h, p_ln2l, p_w1h, p_w1l,
                                           b1, nullptr, nullptr, p_h1h, p_h1l,
                                           MTOK, FFN, DMODEL);

    // 7) FFN2 + bias + residual(res1) -> out
    gemm_mma<3><<<g1024, 256, GEMM_SMEM>>>(p_h1h, p_h1l, p_w2h, p_w2l,
                                           b2, p_res1, out, nullptr, nullptr,
                                           MTOK, DMODEL, FFN);

    (void)in_sizes; (void)n_in; (void)out_size;
}

// round 15
// speedup vs baseline: 1.0493x; 1.0493x over previous
#include <cuda_runtime.h>
#include <cuda_bf16.h>
#include <math.h>
#include <float.h>
#include <stdint.h>

// Problem dims (fixed)
#define BATCH 2
#define SEQ   2048
#define DMODEL 1024
#define NHEAD 16
#define HDIM  64
#define FFN   4096
#define MTOK  (BATCH*SEQ)          // 4096 token rows
#define SEGSZ ((size_t)MTOK*DMODEL)

typedef __nv_bfloat16 bf16;

// ---------------- scratch (allocation-free: __device__ globals) ----------------
__device__ float g_res1[MTOK*DMODEL];

__device__ bf16 g_ln1_hi[MTOK*DMODEL], g_ln1_lo[MTOK*DMODEL];
// fused QKV activations: [Q(pre-scaled 1/8) tok-major | K tok-major | V head-transposed]
__device__ bf16 g_qkv_hi[3*MTOK*DMODEL], g_qkv_lo[3*MTOK*DMODEL];
__device__ bf16 g_ctx_hi[MTOK*DMODEL], g_ctx_lo[MTOK*DMODEL];
__device__ bf16 g_ln2_hi[MTOK*DMODEL], g_ln2_lo[MTOK*DMODEL];
__device__ bf16 g_h1_hi [MTOK*FFN],    g_h1_lo [MTOK*FFN];

__device__ bf16 g_wqkvT_hi[3*DMODEL*DMODEL], g_wqkvT_lo[3*DMODEL*DMODEL];
__device__ bf16 g_woT_hi[DMODEL*DMODEL],     g_woT_lo[DMODEL*DMODEL];
__device__ bf16 g_w1T_hi[DMODEL*FFN],        g_w1T_lo[DMODEL*FFN];
__device__ bf16 g_w2T_hi[FFN*DMODEL],        g_w2T_lo[FFN*DMODEL];

// ---------------- PTX helpers (baseline compute_103-safe: sm_80-era ops only) ----
__device__ __forceinline__ uint32_t smem_u32(const void* p) {
    uint32_t a;
    asm("{ .reg .u64 t; cvta.to.shared.u64 t, %1; cvt.u32.u64 %0, t; }" : "=r"(a) : "l"(p));
    return a;
}
__device__ __forceinline__ void cpa16(uint32_t dst, const void* src) {
    asm volatile("cp.async.cg.shared.global [%0], [%1], 16;" :: "r"(dst), "l"(src));
}
__device__ __forceinline__ void cpa_commit() { asm volatile("cp.async.commit_group;"); }
__device__ __forceinline__ void cpa_wait2()  { asm volatile("cp.async.wait_group 2;" ::: "memory"); }
__device__ __forceinline__ void cpa_wait1()  { asm volatile("cp.async.wait_group 1;" ::: "memory"); }
__device__ __forceinline__ void cpa_wait0()  { asm volatile("cp.async.wait_group 0;" ::: "memory"); }

#define LDSM4(r, a) \
    asm volatile("ldmatrix.sync.aligned.m8n8.x4.shared.b16 {%0,%1,%2,%3}, [%4];" \
        : "=r"((r)[0]), "=r"((r)[1]), "=r"((r)[2]), "=r"((r)[3]) : "r"(a))

#define MMA_BF16(d, a, b0, b1) \
    asm volatile("mma.sync.aligned.m16n8k16.row.col.f32.bf16.bf16.f32 " \
        "{%0,%1,%2,%3}, {%4,%5,%6,%7}, {%8,%9}, {%0,%1,%2,%3};" \
        : "+f"((d)[0]), "+f"((d)[1]), "+f"((d)[2]), "+f"((d)[3]) \
        : "r"((a)[0]), "r"((a)[1]), "r"((a)[2]), "r"((a)[3]), "r"(b0), "r"(b1))

__device__ __forceinline__ float gelu_tanh(float x) {
    const float c = 0.7978845608028654f;
    float t = c * (x + 0.044715f * x * x * x);
    return 0.5f * x * (1.0f + tanhf(t));
}
__device__ __forceinline__ void split_hl(float v, bf16& h, bf16& l) {
    h = __float2bfloat16(v);
    l = __float2bfloat16(v - __bfloat162float(h));
}
__device__ __forceinline__ uint32_t pk2(float x, float y) {
    __nv_bfloat162 t;
    t.x = __float2bfloat16(x);
    t.y = __float2bfloat16(y);
    return *(uint32_t*)&t;
}

// ---------------- LayerNorm -> hi/lo bf16 (torch var ddof=1) ----------------
__global__ __launch_bounds__(256)
void ln_hl_kernel(const float* __restrict__ x, const float* __restrict__ sc,
                  const float* __restrict__ sh, bf16* __restrict__ ohi, bf16* __restrict__ olo)
{
    int row = blockIdx.x;
    int tid = threadIdx.x;
    const float4 a = *(const float4*)&x[(size_t)row * DMODEL + tid * 4];

    float s = a.x + a.y + a.z + a.w;
    float q = a.x*a.x + a.y*a.y + a.z*a.z + a.w*a.w;
    #pragma unroll
    for (int off = 16; off > 0; off >>= 1) {
        s += __shfl_xor_sync(0xFFFFFFFFu, s, off);
        q += __shfl_xor_sync(0xFFFFFFFFu, q, off);
    }
    __shared__ float reds[8], redq[8], stats[2];
    int wid = tid >> 5, lane = tid & 31;
    if (lane == 0) { reds[wid] = s; redq[wid] = q; }
    __syncthreads();
    if (tid == 0) {
        float S = 0.f, Q = 0.f;
        #pragma unroll
        for (int i = 0; i < 8; i++) { S += reds[i]; Q += redq[i]; }
        float mean = S * (1.0f / DMODEL);
        float var  = (Q - S * mean) * (1.0f / (DMODEL - 1));
        stats[0] = mean;
        stats[1] = rsqrtf(var + 1e-5f);
    }
    __syncthreads();
    float mean = stats[0], rstd = stats[1];
    const float4 scv = *(const float4*)&sc[tid * 4];
    const float4 shv = *(const float4*)&sh[tid * 4];
    float o[4];
    o[0] = (a.x - mean) * rstd * scv.x + shv.x;
    o[1] = (a.y - mean) * rstd * scv.y + shv.y;
    o[2] = (a.z - mean) * rstd * scv.z + shv.z;
    o[3] = (a.w - mean) * rstd * scv.w + shv.w;

    union { bf16 b[4]; uint2 u; } uh, ul;
    #pragma unroll
    for (int i = 0; i < 4; i++) split_hl(o[i], uh.b[i], ul.b[i]);
    size_t idx = (size_t)row * DMODEL + tid * 4;
    *(uint2*)&ohi[idx] = uh.u;
    *(uint2*)&olo[idx] = ul.u;
}

// ---------------- weight transpose+convert: W[K,N] f32 -> WT hi/lo bf16 [N,K] ----------------
__global__ __launch_bounds__(256)
void wconvT(const float* __restrict__ W, bf16* __restrict__ ThT, bf16* __restrict__ TlT,
            int K, int N)
{
    __shared__ float t[32][33];
    int tx = threadIdx.x & 31, ty = threadIdx.x >> 5;
    int k0 = blockIdx.y * 32, n0 = blockIdx.x * 32;
    #pragma unroll
    for (int j = 0; j < 4; j++)
        t[ty + j * 8][tx] = W[(size_t)(k0 + ty + j * 8) * N + n0 + tx];
    __syncthreads();
    #pragma unroll
    for (int j = 0; j < 4; j++) {
        int n = n0 + ty + j * 8;
        float v = t[tx][ty + j * 8];
        bf16 h, l; split_hl(v, h, l);
        ThT[(size_t)n * K + k0 + tx] = h;
        TlT[(size_t)n * K + k0 + tx] = l;
    }
}

// batched: wq/wk/wv -> fused qkvT buffer (z=0..2), wo -> woT (z=3); all 1024x1024
__global__ __launch_bounds__(256)
void wconv_qkvo(const float* __restrict__ wq, const float* __restrict__ wk,
                const float* __restrict__ wv, const float* __restrict__ wo,
                bf16* __restrict__ qkvh, bf16* __restrict__ qkvl,
                bf16* __restrict__ woh, bf16* __restrict__ wol)
{
    const int z = blockIdx.z;
    const float* W = (z == 0) ? wq : (z == 1) ? wk : (z == 2) ? wv : wo;
    bf16* Th = (z < 3) ? qkvh + (size_t)z * DMODEL * DMODEL : woh;
    bf16* Tl = (z < 3) ? qkvl + (size_t)z * DMODEL * DMODEL : wol;

    __shared__ float t[32][33];
    int tx = threadIdx.x & 31, ty = threadIdx.x >> 5;
    int k0 = blockIdx.y * 32, n0 = blockIdx.x * 32;
    #pragma unroll
    for (int j = 0; j < 4; j++)
        t[ty + j * 8][tx] = W[(size_t)(k0 + ty + j * 8) * DMODEL + n0 + tx];
    __syncthreads();
    #pragma unroll
    for (int j = 0; j < 4; j++) {
        int n = n0 + ty + j * 8;
        float v = t[tx][ty + j * 8];
        bf16 h, l; split_hl(v, h, l);
        Th[(size_t)n * DMODEL + k0 + tx] = h;
        Tl[(size_t)n * DMODEL + k0 + tx] = l;
    }
}

// ---------------- mma.sync bf16x3 GEMM: C[M,N] = A[M,K] @ B^T (B given as [N,K]) --
// CTA 128x128, BK=64, 256 threads, warp grid 2(M)x4(N), warp tile 64x32.
// 3-stage cp.async, one barrier per chunk (wait -> sync -> prefetch i+2 -> compute).
// D = Ahi*Bhi + Ahi*Blo + Alo*Bhi (rel err ~2^-18). All GEMMs 3-pass (R13 lesson:
// dropping the Alo*Bhi pass on the three weight GEMMs together -> rel_err 1.06e-3).
// EPI: 2 = +bias,gelu -> hi/lo bf16; 3 = +bias +res -> fp32;
//      5 = fused QKV routing (seg0 Q*0.125, seg1 K tok-major; seg2 V head-transposed)
#define TILE_BYTES 16384
#define STAGE_BYTES (4*TILE_BYTES)
#define GEMM_SMEM   (3*STAGE_BYTES)      // 196608

template<int EPI>
__global__ __launch_bounds__(256, 1)
void gemm_mma(const bf16* __restrict__ Ahi, const bf16* __restrict__ Alo,
              const bf16* __restrict__ Bhi, const bf16* __restrict__ Blo,
              const float* __restrict__ bias, const float* __restrict__ res,
              float* __restrict__ Cf, bf16* __restrict__ Chi, bf16* __restrict__ Clo,
              int M, int N, int K)
{
    extern __shared__ char smem[];
    const uint32_t sbase = smem_u32(smem);
    const int tid  = threadIdx.x;
    const int wid  = tid >> 5, lane = tid & 31;
    const int m0 = blockIdx.y * 128, n0 = blockIdx.x * 128;
    const int wm = (wid & 1) * 64, wn = (wid >> 1) * 32;

    const bf16* srcs[4];
    srcs[0] = Ahi + (size_t)m0 * K;
    srcs[1] = Alo + (size_t)m0 * K;
    srcs[2] = Bhi + (size_t)n0 * K;
    srcs[3] = Blo + (size_t)n0 * K;

    float acc[4][4][4];
    #pragma unroll
    for (int a = 0; a < 4; a++)
        #pragma unroll
        for (int b = 0; b < 4; b++)
            #pragma unroll
            for (int c = 0; c < 4; c++) acc[a][b][c] = 0.f;

    const int NC = K >> 6;

    auto load_stage = [&](int chunk, int stage) {
        const int k0 = chunk << 6;
        const uint32_t base = sbase + stage * STAGE_BYTES;
        #pragma unroll
        for (int j = 0; j < 16; j++) {
            const int tile = j >> 2;
            const int cid  = ((j & 3) << 8) + tid;
            const int row  = cid >> 3;
            const int c    = cid & 7;
            uint32_t dst = base + tile * TILE_BYTES + row * 128 + ((c ^ (row & 7)) << 4);
            cpa16(dst, srcs[tile] + (size_t)row * K + k0 + c * 8);
        }
        cpa_commit();
    };

    load_stage(0, 0);
    load_stage(1, 1);

    for (int i = 0; i < NC; i++) {
        if (i + 1 < NC) cpa_wait1(); else cpa_wait0();   // own chunk-i group done
        __syncthreads();                                 // publish; fence prev reads
        if (i + 2 < NC) load_stage(i + 2, (i + 2) % 3);  // writes stage (i-1)%3: safe
        const uint32_t tb = sbase + (i % 3) * STAGE_BYTES;

        #pragma unroll
        for (int ks = 0; ks < 4; ks++) {
            uint32_t ah[4][4], al[4][4], bh[2][4], bl[2][4];
            #pragma unroll
            for (int mt = 0; mt < 4; mt++) {
                int row = wm + mt * 16 + (lane & 15);
                int kg  = ks * 2 + (lane >> 4);
                uint32_t off = row * 128 + ((kg ^ (row & 7)) << 4);
                LDSM4(ah[mt], tb + off);
                LDSM4(al[mt], tb + TILE_BYTES + off);
            }
            #pragma unroll
            for (int bt = 0; bt < 2; bt++) {
                int row = wn + bt * 16 + ((lane >> 4) << 3) + (lane & 7);
                int kg  = ks * 2 + ((lane >> 3) & 1);
                uint32_t off = row * 128 + ((kg ^ (row & 7)) << 4);
                LDSM4(bh[bt], tb + 2 * TILE_BYTES + off);
                LDSM4(bl[bt], tb + 3 * TILE_BYTES + off);
            }
            #pragma unroll
            for (int mt = 0; mt < 4; mt++)
                #pragma unroll
                for (int nt = 0; nt < 4; nt++)
                    MMA_BF16(acc[mt][nt], ah[mt],
                             bh[nt >> 1][(nt & 1) * 2], bh[nt >> 1][(nt & 1) * 2 + 1]);
            #pragma unroll
            for (int mt = 0; mt < 4; mt++)
                #pragma unroll
                for (int nt = 0; nt < 4; nt++)
                    MMA_BF16(acc[mt][nt], ah[mt],
                             bl[nt >> 1][(nt & 1) * 2], bl[nt >> 1][(nt & 1) * 2 + 1]);
            #pragma unroll
            for (int mt = 0; mt < 4; mt++)
                #pragma unroll
                for (int nt = 0; nt < 4; nt++)
                    MMA_BF16(acc[mt][nt], al[mt],
                             bh[nt >> 1][(nt & 1) * 2], bh[nt >> 1][(nt & 1) * 2 + 1]);
        }
    }

    // ---- epilogue (fragment: rows g, g+8; cols 2t, 2t+1) ----
    const int g = lane >> 2, t = lane & 3;
    #pragma unroll
    for (int mt = 0; mt < 4; mt++) {
        #pragma unroll
        for (int nt = 0; nt < 4; nt++) {
            const int gr0 = m0 + wm + mt * 16 + g;
            const int gr1 = gr0 + 8;
            const int gc  = n0 + wn + nt * 8 + 2 * t;
            float v00 = acc[mt][nt][0], v01 = acc[mt][nt][1];
            float v10 = acc[mt][nt][2], v11 = acc[mt][nt][3];
            if (EPI == 3) {
                const float2 bv  = *(const float2*)&bias[gc];
                const float2 r0v = *(const float2*)&res[(size_t)gr0 * N + gc];
                const float2 r1v = *(const float2*)&res[(size_t)gr1 * N + gc];
                *(float2*)&Cf[(size_t)gr0 * N + gc] =
                    make_float2(v00 + bv.x + r0v.x, v01 + bv.y + r0v.y);
                *(float2*)&Cf[(size_t)gr1 * N + gc] =
                    make_float2(v10 + bv.x + r1v.x, v11 + bv.y + r1v.y);
            } else if (EPI == 2) {
                const float2 bv = *(const float2*)&bias[gc];
                float x00 = gelu_tanh(v00 + bv.x), x01 = gelu_tanh(v01 + bv.y);
                float x10 = gelu_tanh(v10 + bv.x), x11 = gelu_tanh(v11 + bv.y);
                __nv_bfloat162 h0, l0, h1, l1;
                split_hl(x00, h0.x, l0.x); split_hl(x01, h0.y, l0.y);
                split_hl(x10, h1.x, l1.x); split_hl(x11, h1.y, l1.y);
                *(__nv_bfloat162*)&Chi[(size_t)gr0 * N + gc] = h0;
                *(__nv_bfloat162*)&Clo[(size_t)gr0 * N + gc] = l0;
                *(__nv_bfloat162*)&Chi[(size_t)gr1 * N + gc] = h1;
                *(__nv_bfloat162*)&Clo[(size_t)gr1 * N + gc] = l1;
            } else { // EPI == 5: fused QKV
                const int seg = gc >> 10;       // constant per CTA
                const int col = gc & 1023;
                if (seg == 0) { v00 *= 0.125f; v01 *= 0.125f; v10 *= 0.125f; v11 *= 0.125f; }
                if (seg < 2) {
                    const size_t base = (size_t)seg * SEGSZ;
                    __nv_bfloat162 h0, l0, h1, l1;
                    split_hl(v00, h0.x, l0.x); split_hl(v01, h0.y, l0.y);
                    split_hl(v10, h1.x, l1.x); split_hl(v11, h1.y, l1.y);
                    *(__nv_bfloat162*)&Chi[base + (size_t)gr0 * DMODEL + col] = h0;
                    *(__nv_bfloat162*)&Clo[base + (size_t)gr0 * DMODEL + col] = l0;
                    *(__nv_bfloat162*)&Chi[base + (size_t)gr1 * DMODEL + col] = h1;
                    *(__nv_bfloat162*)&Clo[base + (size_t)gr1 * DMODEL + col] = l1;
                } else {    // V head-transposed: [b*16+h][d][s]
                    #pragma unroll
                    for (int e = 0; e < 4; e++) {
                        int gr = (e < 2) ? gr0 : gr1;
                        int cc = col + (e & 1);
                        float v = (e == 0) ? v00 : (e == 1) ? v01 : (e == 2) ? v10 : v11;
                        int b = gr >> 11, s = gr & 2047;
                        int h = cc >> 6, d = cc & 63;
                        size_t o = 2 * SEGSZ + ((size_t)((b * 16 + h) * 64 + d)) * 2048 + s;
                        bf16 hh, ll; split_hl(v, hh, ll);
                        Chi[o] = hh;
                        Clo[o] = ll;
                    }
                }
            }
        }
    }
}

// ---------------- mma.sync flash attention (bf16x2, causal) -> ctx hi/lo ----------
// CTA: 128 q-rows x one (b,h). 256 threads = 8 warps x 16 rows. KV tile = 64 keys.
// Q pre-scaled by 1/8. 2-pass compensation: S = Qh*Kh + Qh*Kl (Ql pass dropped);
// O += P*Vh + P*Vl with P rounded to bf16 (Pl pass dropped). Residual-stream
// dilution (~x0.13) bounds the added error at ~3e-4 final.
// smem: Qhi@0 (16KB); stage s @16384+s*32768: Khi,Klo,Vhi,Vlo (8KB each)
#define ATT_SMEM (16384 + 2*32768)

__global__ __launch_bounds__(256, 1)
void attn_mma(const bf16* __restrict__ qhi,
              const bf16* __restrict__ khi, const bf16* __restrict__ klo,
              const bf16* __restrict__ vthi, const bf16* __restrict__ vtlo,
              bf16* __restrict__ chi, bf16* __restrict__ clo)
{
    extern __shared__ char smem[];
    const uint32_t sbase = smem_u32(smem);
    const int tid  = threadIdx.x;
    const int wid  = tid >> 5, lane = tid & 31;
    const int g = lane >> 2, t = lane & 3;
    const int bh = blockIdx.y;
    const int b = bh >> 4, h = bh & 15;
    const int m0 = (gridDim.x - 1 - blockIdx.x) * 128;   // longest blocks first
    const int nit = m0 / 64 + 2;

    // ---- load Q tile (128 rows, hi only) ----
    {
        const bf16* qs = qhi + ((size_t)(b * SEQ + m0)) * DMODEL + h * 64;
        #pragma unroll
        for (int j = 0; j < 4; j++) {
            int cid = j * 256 + tid;
            int row = cid >> 3, c = cid & 7;
            cpa16(sbase + row * 128 + ((c ^ (row & 7)) << 4),
                  qs + (size_t)row * DMODEL + c * 8);
        }
        cpa_commit();
    }

    auto load_kv = [&](int it, int stage) {
        const int n0 = it * 64;
        const uint32_t base = sbase + 16384 + stage * 32768;
        const bf16* ks_[2] = { khi + ((size_t)(b * SEQ + n0)) * DMODEL + h * 64,
                               klo + ((size_t)(b * SEQ + n0)) * DMODEL + h * 64 };
        const bf16* vs_[2] = { vthi + ((size_t)(bh * 64)) * 2048 + n0,
                               vtlo + ((size_t)(bh * 64)) * 2048 + n0 };
        #pragma unroll
        for (int tl = 0; tl < 2; tl++)
            #pragma unroll
            for (int j = 0; j < 2; j++) {
                int cid = j * 256 + tid;
                int row = cid >> 3, c = cid & 7;
                uint32_t sw = row * 128 + ((c ^ (row & 7)) << 4);
                cpa16(base + tl * 8192 + sw,         ks_[tl] + (size_t)row * DMODEL + c * 8);
                cpa16(base + 16384 + tl * 8192 + sw, vs_[tl] + (size_t)row * 2048 + c * 8);
            }
        cpa_commit();
    };

    load_kv(0, 0);
    load_kv(1, 1);

    // Q fragments (constant across iters)
    cpa_wait2();
    __syncthreads();
    uint32_t qh[4][4];
    #pragma unroll
    for (int ks = 0; ks < 4; ks++) {
        int row = wid * 16 + (lane & 15);
        int kg  = ks * 2 + (lane >> 4);
        uint32_t off = row * 128 + ((kg ^ (row & 7)) << 4);
        LDSM4(qh[ks], sbase + off);
    }

    float m[2] = { -INFINITY, -INFINITY };
    float l[2] = { 0.f, 0.f };
    float acc_o[8][4];
    #pragma unroll
    for (int i = 0; i < 8; i++)
        #pragma unroll
        for (int c = 0; c < 4; c++) acc_o[i][c] = 0.f;

    const int rowL64 = (wid & 3) * 16 + g;
    const int wdiag  = (wid < 4) ? (nit - 2) : (nit - 1);

    for (int it = 0; it < nit; it++) {
        const int rem = nit - 1 - it;
        if (rem >= 1) cpa_wait1(); else cpa_wait0();
        __syncthreads();
        const uint32_t kb = sbase + 16384 + (it & 1) * 32768;
        const uint32_t vb = kb + 16384;
        const bool active = !(wid < 4 && it == nit - 1);

        if (active) {
            const bool diag = (it == wdiag);

            // ---- S = Q K^T (2-pass: Qh*Kh + Qh*Kl) ----
            float s[8][4];
            #pragma unroll
            for (int i = 0; i < 8; i++)
                #pragma unroll
                for (int c = 0; c < 4; c++) s[i][c] = 0.f;

            #pragma unroll
            for (int ks = 0; ks < 4; ks++) {
                uint32_t kh[4][4], kl[4][4];
                #pragma unroll
                for (int bt = 0; bt < 4; bt++) {
                    int row = bt * 16 + ((lane >> 4) << 3) + (lane & 7);
                    int kg  = ks * 2 + ((lane >> 3) & 1);
                    uint32_t off = row * 128 + ((kg ^ (row & 7)) << 4);
                    LDSM4(kh[bt], kb + off);
                    LDSM4(kl[bt], kb + 8192 + off);
                }
                #pragma unroll
                for (int nt = 0; nt < 8; nt++)
                    MMA_BF16(s[nt], qh[ks],
                             kh[nt >> 1][(nt & 1) * 2], kh[nt >> 1][(nt & 1) * 2 + 1]);
                #pragma unroll
                for (int nt = 0; nt < 8; nt++)
                    MMA_BF16(s[nt], qh[ks],
                             kl[nt >> 1][(nt & 1) * 2], kl[nt >> 1][(nt & 1) * 2 + 1]);
            }

            // ---- causal mask + online softmax (Q pre-scaled) ----
            #pragma unroll
            for (int nt = 0; nt < 8; nt++) {
                #pragma unroll
                for (int c = 0; c < 4; c++) {
                    int colL = nt * 8 + 2 * t + (c & 1);
                    int rowL = rowL64 + ((c >> 1) << 3);
                    if (diag && colL > rowL) s[nt][c] = -INFINITY;
                }
            }
            float mx0 = -INFINITY, mx1 = -INFINITY;
            #pragma unroll
            for (int nt = 0; nt < 8; nt++) {
                mx0 = fmaxf(mx0, fmaxf(s[nt][0], s[nt][1]));
                mx1 = fmaxf(mx1, fmaxf(s[nt][2], s[nt][3]));
            }
            mx0 = fmaxf(mx0, __shfl_xor_sync(0xFFFFFFFFu, mx0, 1));
            mx0 = fmaxf(mx0, __shfl_xor_sync(0xFFFFFFFFu, mx0, 2));
            mx1 = fmaxf(mx1, __shfl_xor_sync(0xFFFFFFFFu, mx1, 1));
            mx1 = fmaxf(mx1, __shfl_xor_sync(0xFFFFFFFFu, mx1, 2));
            float mn0 = fmaxf(m[0], mx0), mn1 = fmaxf(m[1], mx1);
            float a0 = __expf(m[0] - mn0), a1 = __expf(m[1] - mn1);
            m[0] = mn0; m[1] = mn1;
            #pragma unroll
            for (int i = 0; i < 8; i++) {
                acc_o[i][0] *= a0; acc_o[i][1] *= a0;
                acc_o[i][2] *= a1; acc_o[i][3] *= a1;
            }
            float sum0 = 0.f, sum1 = 0.f;
            float p[8][4];
            #pragma unroll
            for (int nt = 0; nt < 8; nt++) {
                p[nt][0] = __expf(s[nt][0] - mn0); p[nt][1] = __expf(s[nt][1] - mn0);
                p[nt][2] = __expf(s[nt][2] - mn1); p[nt][3] = __expf(s[nt][3] - mn1);
                sum0 += p[nt][0] + p[nt][1];
                sum1 += p[nt][2] + p[nt][3];
            }
            sum0 += __shfl_xor_sync(0xFFFFFFFFu, sum0, 1);
            sum0 += __shfl_xor_sync(0xFFFFFFFFu, sum0, 2);
            sum1 += __shfl_xor_sync(0xFFFFFFFFu, sum1, 1);
            sum1 += __shfl_xor_sync(0xFFFFFFFFu, sum1, 2);
            l[0] = l[0] * a0 + sum0;
            l[1] = l[1] * a1 + sum1;

            // ---- O += P V (2-pass: P*Vh + P*Vl; P rounded to bf16) ----
            #pragma unroll
            for (int ks2 = 0; ks2 < 4; ks2++) {
                uint32_t pah[4];
                #pragma unroll
                for (int e = 0; e < 2; e++) {
                    int nt = 2 * ks2 + e;
                    pah[e * 2 + 0] = pk2(p[nt][0], p[nt][1]);
                    pah[e * 2 + 1] = pk2(p[nt][2], p[nt][3]);
                }

                uint32_t vh[4][4], vl[4][4];
                #pragma unroll
                for (int dt = 0; dt < 4; dt++) {
                    int row = dt * 16 + ((lane >> 4) << 3) + (lane & 7);
                    int kg  = ks2 * 2 + ((lane >> 3) & 1);
                    uint32_t off = row * 128 + ((kg ^ (row & 7)) << 4);
                    LDSM4(vh[dt], vb + off);
                    LDSM4(vl[dt], vb + 8192 + off);
                }
                #pragma unroll
                for (int nt = 0; nt < 8; nt++)
                    MMA_BF16(acc_o[nt], pah,
                             vh[nt >> 1][(nt & 1) * 2], vh[nt >> 1][(nt & 1) * 2 + 1]);
                #pragma unroll
                for (int nt = 0; nt < 8; nt++)
                    MMA_BF16(acc_o[nt], pah,
                             vl[nt >> 1][(nt & 1) * 2], vl[nt >> 1][(nt & 1) * 2 + 1]);
            }
        }

        __syncthreads();
        if (it + 2 < nit) load_kv(it + 2, it & 1);
    }

    // ---- epilogue ----
    float inv0 = 1.0f / l[0], inv1 = 1.0f / l[1];
    const size_t gr0 = (size_t)(b * SEQ + m0 + wid * 16 + g) * DMODEL + h * 64;
    const size_t gr1 = gr0 + 8 * DMODEL;
    #pragma unroll
    for (int nt = 0; nt < 8; nt++) {
        int gc = nt * 8 + 2 * t;
        __nv_bfloat162 h0, l0h, h1, l1h;
        split_hl(acc_o[nt][0] * inv0, h0.x, l0h.x);
        split_hl(acc_o[nt][1] * inv0, h0.y, l0h.y);
        split_hl(acc_o[nt][2] * inv1, h1.x, l1h.x);
        split_hl(acc_o[nt][3] * inv1, h1.y, l1h.y);
        *(__nv_bfloat162*)&chi[gr0 + gc] = h0;
        *(__nv_bfloat162*)&clo[gr0 + gc] = l0h;
        *(__nv_bfloat162*)&chi[gr1 + gc] = h1;
        *(__nv_bfloat162*)&clo[gr1 + gc] = l1h;
    }
}

// ---------------- launch ----------------
extern "C" void kernel_launch(void* const* d_in, const int* in_sizes, int n_in,
                              void* d_out, int out_size)
{
    const float* x         = (const float*)d_in[0];
    const float* ln1_scale = (const float*)d_in[1];
    const float* ln1_shift = (const float*)d_in[2];
    const float* wq        = (const float*)d_in[3];
    const float* wk        = (const float*)d_in[4];
    const float* wv        = (const float*)d_in[5];
    const float* w_out     = (const float*)d_in[6];
    const float* b_out     = (const float*)d_in[7];
    const float* ln2_scale = (const float*)d_in[8];
    const float* ln2_shift = (const float*)d_in[9];
    const float* w1        = (const float*)d_in[10];
    const float* b1        = (const float*)d_in[11];
    const float* w2        = (const float*)d_in[12];
    const float* b2        = (const float*)d_in[13];
    float* out = (float*)d_out;

    float *p_res1;
    bf16 *p_ln1h, *p_ln1l, *p_qkvh, *p_qkvl;
    bf16 *p_ctxh, *p_ctxl, *p_ln2h, *p_ln2l, *p_h1h, *p_h1l;
    bf16 *p_wqkvh, *p_wqkvl, *p_woh, *p_wol, *p_w1h, *p_w1l, *p_w2h, *p_w2l;
    cudaGetSymbolAddress((void**)&p_res1,  g_res1);
    cudaGetSymbolAddress((void**)&p_ln1h,  g_ln1_hi);
    cudaGetSymbolAddress((void**)&p_ln1l,  g_ln1_lo);
    cudaGetSymbolAddress((void**)&p_qkvh,  g_qkv_hi);
    cudaGetSymbolAddress((void**)&p_qkvl,  g_qkv_lo);
    cudaGetSymbolAddress((void**)&p_ctxh,  g_ctx_hi);
    cudaGetSymbolAddress((void**)&p_ctxl,  g_ctx_lo);
    cudaGetSymbolAddress((void**)&p_ln2h,  g_ln2_hi);
    cudaGetSymbolAddress((void**)&p_ln2l,  g_ln2_lo);
    cudaGetSymbolAddress((void**)&p_h1h,   g_h1_hi);
    cudaGetSymbolAddress((void**)&p_h1l,   g_h1_lo);
    cudaGetSymbolAddress((void**)&p_wqkvh, g_wqkvT_hi);
    cudaGetSymbolAddress((void**)&p_wqkvl, g_wqkvT_lo);
    cudaGetSymbolAddress((void**)&p_woh,   g_woT_hi);
    cudaGetSymbolAddress((void**)&p_wol,   g_woT_lo);
    cudaGetSymbolAddress((void**)&p_w1h,   g_w1T_hi);
    cudaGetSymbolAddress((void**)&p_w1l,   g_w1T_lo);
    cudaGetSymbolAddress((void**)&p_w2h,   g_w2T_hi);
    cudaGetSymbolAddress((void**)&p_w2l,   g_w2T_lo);

    static bool attr_set = false;
    if (!attr_set) {
        cudaFuncSetAttribute(attn_mma,    cudaFuncAttributeMaxDynamicSharedMemorySize, ATT_SMEM);
        cudaFuncSetAttribute(gemm_mma<2>, cudaFuncAttributeMaxDynamicSharedMemorySize, GEMM_SMEM);
        cudaFuncSetAttribute(gemm_mma<3>, cudaFuncAttributeMaxDynamicSharedMemorySize, GEMM_SMEM);
        cudaFuncSetAttribute(gemm_mma<5>, cudaFuncAttributeMaxDynamicSharedMemorySize, GEMM_SMEM);
        attr_set = true;
    }

    // 0) weight transpose + hi/lo convert
    wconv_qkvo<<<dim3(DMODEL/32, DMODEL/32, 4), 256>>>(wq, wk, wv, w_out,
                                                       p_wqkvh, p_wqkvl, p_woh, p_wol);
    wconvT<<<dim3(FFN/32,    DMODEL/32), 256>>>(w1, p_w1h, p_w1l, DMODEL, FFN);
    wconvT<<<dim3(DMODEL/32, FFN/32),    256>>>(w2, p_w2h, p_w2l, FFN,    DMODEL);

    // 1) LN1 -> hi/lo
    ln_hl_kernel<<<MTOK, 256>>>(x, ln1_scale, ln1_shift, p_ln1h, p_ln1l);

    dim3 gQKV(3*DMODEL/128, MTOK/128);
    dim3 g1024(DMODEL/128,  MTOK/128);
    dim3 g4096(FFN/128,     MTOK/128);

    // 2) fused QKV projection (3-pass) -> hi/lo bf16 (Q pre-scaled 1/8; V head-transposed)
    gemm_mma<5><<<gQKV, 256, GEMM_SMEM>>>(p_ln1h, p_ln1l, p_wqkvh, p_wqkvl,
                                          nullptr, nullptr, nullptr, p_qkvh, p_qkvl,
                                          MTOK, 3*DMODEL, DMODEL);

    // 3) attention (tensor core, 2-pass compensated) -> ctx hi/lo
    dim3 gAttn(SEQ/128, BATCH*NHEAD);
    attn_mma<<<gAttn, 256, ATT_SMEM>>>(p_qkvh,
                                       p_qkvh + SEGSZ,    p_qkvl + SEGSZ,
                                       p_qkvh + 2*SEGSZ,  p_qkvl + 2*SEGSZ,
                                       p_ctxh, p_ctxl);

    // 4) out projection (3-pass) + bias + residual(x) -> res1 (fp32)
    gemm_mma<3><<<g1024, 256, GEMM_SMEM>>>(p_ctxh, p_ctxl, p_woh, p_wol,
                                           b_out, x, p_res1, nullptr, nullptr,
                                           MTOK, DMODEL, DMODEL);

    // 5) LN2 -> hi/lo
    ln_hl_kernel<<<MTOK, 256>>>(p_res1, ln2_scale, ln2_shift, p_ln2h, p_ln2l);

    // 6) FFN1 (3-pass) + bias + gelu -> h1 hi/lo
    gemm_mma<2><<<g4096, 256, GEMM_SMEM>>>(p_ln2h, p_ln2l, p_w1h, p_w1l,
                                           b1, nullptr, nullptr, p_h1h, p_h1l,
                                           MTOK, FFN, DMODEL);

    // 7) FFN2 (3-pass) + bias + residual(res1) -> out
    gemm_mma<3><<<g1024, 256, GEMM_SMEM>>>(p_h1h, p_h1l, p_w2h, p_w2l,
                                           b2, p_res1, out, nullptr, nullptr,
                                           MTOK, DMODEL, FFN);

    (void)in_sizes; (void)n_in; (void)out_size;
}

// round 16
// speedup vs baseline: 1.1103x; 1.0581x over previous
#include <cuda_runtime.h>
#include <cuda_bf16.h>
#include <math.h>
#include <float.h>
#include <stdint.h>

// Problem dims (fixed)
#define BATCH 2
#define SEQ   2048
#define DMODEL 1024
#define NHEAD 16
#define HDIM  64
#define FFN   4096
#define MTOK  (BATCH*SEQ)          // 4096 token rows
#define SEGSZ ((size_t)MTOK*DMODEL)

typedef __nv_bfloat16 bf16;

// ---------------- scratch (allocation-free: __device__ globals) ----------------
__device__ float g_res1[MTOK*DMODEL];

__device__ bf16 g_ln1_hi[MTOK*DMODEL], g_ln1_lo[MTOK*DMODEL];
// fused QKV activations: [Q(pre-scaled 1/8) tok-major | K tok-major | V head-transposed]
__device__ bf16 g_qkv_hi[3*MTOK*DMODEL], g_qkv_lo[3*MTOK*DMODEL];
__device__ bf16 g_ctx_hi[MTOK*DMODEL], g_ctx_lo[MTOK*DMODEL];
__device__ bf16 g_ln2_hi[MTOK*DMODEL], g_ln2_lo[MTOK*DMODEL];
__device__ bf16 g_h1_hi [MTOK*FFN],    g_h1_lo [MTOK*FFN];

__device__ bf16 g_wqkvT_hi[3*DMODEL*DMODEL], g_wqkvT_lo[3*DMODEL*DMODEL];
__device__ bf16 g_woT_hi[DMODEL*DMODEL],     g_woT_lo[DMODEL*DMODEL];
__device__ bf16 g_w1T_hi[DMODEL*FFN],        g_w1T_lo[DMODEL*FFN];
__device__ bf16 g_w2T_hi[FFN*DMODEL],        g_w2T_lo[FFN*DMODEL];

// ---------------- PTX helpers (baseline compute_103-safe: sm_80-era ops only) ----
__device__ __forceinline__ uint32_t smem_u32(const void* p) {
    uint32_t a;
    asm("{ .reg .u64 t; cvta.to.shared.u64 t, %1; cvt.u32.u64 %0, t; }" : "=r"(a) : "l"(p));
    return a;
}
__device__ __forceinline__ void cpa16(uint32_t dst, const void* src) {
    asm volatile("cp.async.cg.shared.global [%0], [%1], 16;" :: "r"(dst), "l"(src));
}
__device__ __forceinline__ void cpa_commit() { asm volatile("cp.async.commit_group;"); }
__device__ __forceinline__ void cpa_wait2()  { asm volatile("cp.async.wait_group 2;" ::: "memory"); }
__device__ __forceinline__ void cpa_wait1()  { asm volatile("cp.async.wait_group 1;" ::: "memory"); }
__device__ __forceinline__ void cpa_wait0()  { asm volatile("cp.async.wait_group 0;" ::: "memory"); }

#define LDSM4(r, a) \
    asm volatile("ldmatrix.sync.aligned.m8n8.x4.shared.b16 {%0,%1,%2,%3}, [%4];" \
        : "=r"((r)[0]), "=r"((r)[1]), "=r"((r)[2]), "=r"((r)[3]) : "r"(a))

#define MMA_BF16(d, a, b0, b1) \
    asm volatile("mma.sync.aligned.m16n8k16.row.col.f32.bf16.bf16.f32 " \
        "{%0,%1,%2,%3}, {%4,%5,%6,%7}, {%8,%9}, {%0,%1,%2,%3};" \
        : "+f"((d)[0]), "+f"((d)[1]), "+f"((d)[2]), "+f"((d)[3]) \
        : "r"((a)[0]), "r"((a)[1]), "r"((a)[2]), "r"((a)[3]), "r"(b0), "r"(b1))

__device__ __forceinline__ float gelu_tanh(float x) {
    const float c = 0.7978845608028654f;
    float t = c * (x + 0.044715f * x * x * x);
    return 0.5f * x * (1.0f + tanhf(t));
}
__device__ __forceinline__ void split_hl(float v, bf16& h, bf16& l) {
    h = __float2bfloat16(v);
    l = __float2bfloat16(v - __bfloat162float(h));
}
__device__ __forceinline__ uint32_t pk2(float x, float y) {
    __nv_bfloat162 t;
    t.x = __float2bfloat16(x);
    t.y = __float2bfloat16(y);
    return *(uint32_t*)&t;
}

// ---------------- LayerNorm -> hi/lo bf16 (torch var ddof=1) ----------------
__global__ __launch_bounds__(256)
void ln_hl_kernel(const float* __restrict__ x, const float* __restrict__ sc,
                  const float* __restrict__ sh, bf16* __restrict__ ohi, bf16* __restrict__ olo)
{
    int row = blockIdx.x;
    int tid = threadIdx.x;
    const float4 a = *(const float4*)&x[(size_t)row * DMODEL + tid * 4];

    float s = a.x + a.y + a.z + a.w;
    float q = a.x*a.x + a.y*a.y + a.z*a.z + a.w*a.w;
    #pragma unroll
    for (int off = 16; off > 0; off >>= 1) {
        s += __shfl_xor_sync(0xFFFFFFFFu, s, off);
        q += __shfl_xor_sync(0xFFFFFFFFu, q, off);
    }
    __shared__ float reds[8], redq[8], stats[2];
    int wid = tid >> 5, lane = tid & 31;
    if (lane == 0) { reds[wid] = s; redq[wid] = q; }
    __syncthreads();
    if (tid == 0) {
        float S = 0.f, Q = 0.f;
        #pragma unroll
        for (int i = 0; i < 8; i++) { S += reds[i]; Q += redq[i]; }
        float mean = S * (1.0f / DMODEL);
        float var  = (Q - S * mean) * (1.0f / (DMODEL - 1));
        stats[0] = mean;
        stats[1] = rsqrtf(var + 1e-5f);
    }
    __syncthreads();
    float mean = stats[0], rstd = stats[1];
    const float4 scv = *(const float4*)&sc[tid * 4];
    const float4 shv = *(const float4*)&sh[tid * 4];
    float o[4];
    o[0] = (a.x - mean) * rstd * scv.x + shv.x;
    o[1] = (a.y - mean) * rstd * scv.y + shv.y;
    o[2] = (a.z - mean) * rstd * scv.z + shv.z;
    o[3] = (a.w - mean) * rstd * scv.w + shv.w;

    union { bf16 b[4]; uint2 u; } uh, ul;
    #pragma unroll
    for (int i = 0; i < 4; i++) split_hl(o[i], uh.b[i], ul.b[i]);
    size_t idx = (size_t)row * DMODEL + tid * 4;
    *(uint2*)&ohi[idx] = uh.u;
    *(uint2*)&olo[idx] = ul.u;
}

// ---------------- weight transpose+convert: W[K,N] f32 -> WT hi/lo bf16 [N,K] ----------------
__global__ __launch_bounds__(256)
void wconvT(const float* __restrict__ W, bf16* __restrict__ ThT, bf16* __restrict__ TlT,
            int K, int N)
{
    __shared__ float t[32][33];
    int tx = threadIdx.x & 31, ty = threadIdx.x >> 5;
    int k0 = blockIdx.y * 32, n0 = blockIdx.x * 32;
    #pragma unroll
    for (int j = 0; j < 4; j++)
        t[ty + j * 8][tx] = W[(size_t)(k0 + ty + j * 8) * N + n0 + tx];
    __syncthreads();
    #pragma unroll
    for (int j = 0; j < 4; j++) {
        int n = n0 + ty + j * 8;
        float v = t[tx][ty + j * 8];
        bf16 h, l; split_hl(v, h, l);
        ThT[(size_t)n * K + k0 + tx] = h;
        TlT[(size_t)n * K + k0 + tx] = l;
    }
}

// batched: wq/wk/wv -> fused qkvT buffer (z=0..2), wo -> woT (z=3); all 1024x1024
__global__ __launch_bounds__(256)
void wconv_qkvo(const float* __restrict__ wq, const float* __restrict__ wk,
                const float* __restrict__ wv, const float* __restrict__ wo,
                bf16* __restrict__ qkvh, bf16* __restrict__ qkvl,
                bf16* __restrict__ woh, bf16* __restrict__ wol)
{
    const int z = blockIdx.z;
    const float* W = (z == 0) ? wq : (z == 1) ? wk : (z == 2) ? wv : wo;
    bf16* Th = (z < 3) ? qkvh + (size_t)z * DMODEL * DMODEL : woh;
    bf16* Tl = (z < 3) ? qkvl + (size_t)z * DMODEL * DMODEL : wol;

    __shared__ float t[32][33];
    int tx = threadIdx.x & 31, ty = threadIdx.x >> 5;
    int k0 = blockIdx.y * 32, n0 = blockIdx.x * 32;
    #pragma unroll
    for (int j = 0; j < 4; j++)
        t[ty + j * 8][tx] = W[(size_t)(k0 + ty + j * 8) * DMODEL + n0 + tx];
    __syncthreads();
    #pragma unroll
    for (int j = 0; j < 4; j++) {
        int n = n0 + ty + j * 8;
        float v = t[tx][ty + j * 8];
        bf16 h, l; split_hl(v, h, l);
        Th[(size_t)n * DMODEL + k0 + tx] = h;
        Tl[(size_t)n * DMODEL + k0 + tx] = l;
    }
}

// ---------------- mma.sync bf16 GEMM: C[M,N] = A[M,K] @ B^T (B given as [N,K]) ----
// CTA 128x128, BK=64, 256 threads, warp grid 2(M)x4(N), warp tile 64x32.
// 3-stage cp.async, one barrier per chunk (wait -> sync -> prefetch i+2 -> compute).
// PASSES=3: D = Ahi*Bhi + Ahi*Blo + Alo*Bhi (rel err ~2^-18)
// PASSES=2: D = Ahi*Bhi + Ahi*Blo (drops activation-lo term; used ONLY for QKV,
//   whose error is softmax-damped — R15 measured this error class at 4.3e-5.
//   R13 lesson: do NOT use on wo/FFN1/FFN2 (residual-direct, ~6e-4 each).)
// EPI: 2 = +bias,gelu -> hi/lo bf16; 3 = +bias +res -> fp32;
//      5 = fused QKV routing (seg0 Q*0.125, seg1 K tok-major; seg2 V head-transposed)
#define TILE_BYTES 16384
#define STAGE_BYTES (4*TILE_BYTES)
#define GEMM_SMEM   (3*STAGE_BYTES)      // 196608

template<int EPI, int PASSES>
__global__ __launch_bounds__(256, 1)
void gemm_mma(const bf16* __restrict__ Ahi, const bf16* __restrict__ Alo,
              const bf16* __restrict__ Bhi, const bf16* __restrict__ Blo,
              const float* __restrict__ bias, const float* __restrict__ res,
              float* __restrict__ Cf, bf16* __restrict__ Chi, bf16* __restrict__ Clo,
              int M, int N, int K)
{
    extern __shared__ char smem[];
    const uint32_t sbase = smem_u32(smem);
    const int tid  = threadIdx.x;
    const int wid  = tid >> 5, lane = tid & 31;
    const int m0 = blockIdx.y * 128, n0 = blockIdx.x * 128;
    const int wm = (wid & 1) * 64, wn = (wid >> 1) * 32;

    const bf16* srcs[4];
    srcs[0] = Ahi + (size_t)m0 * K;
    srcs[1] = Alo + (size_t)m0 * K;
    srcs[2] = Bhi + (size_t)n0 * K;
    srcs[3] = Blo + (size_t)n0 * K;

    float acc[4][4][4];
    #pragma unroll
    for (int a = 0; a < 4; a++)
        #pragma unroll
        for (int b = 0; b < 4; b++)
            #pragma unroll
            for (int c = 0; c < 4; c++) acc[a][b][c] = 0.f;

    const int NC = K >> 6;

    auto load_stage = [&](int chunk, int stage) {
        const int k0 = chunk << 6;
        const uint32_t base = sbase + stage * STAGE_BYTES;
        #pragma unroll
        for (int j = 0; j < 16; j++) {
            const int tile = j >> 2;
            const int cid  = ((j & 3) << 8) + tid;
            const int row  = cid >> 3;
            const int c    = cid & 7;
            uint32_t dst = base + tile * TILE_BYTES + row * 128 + ((c ^ (row & 7)) << 4);
            cpa16(dst, srcs[tile] + (size_t)row * K + k0 + c * 8);
        }
        cpa_commit();
    };

    load_stage(0, 0);
    load_stage(1, 1);

    for (int i = 0; i < NC; i++) {
        if (i + 1 < NC) cpa_wait1(); else cpa_wait0();   // own chunk-i group done
        __syncthreads();                                 // publish; fence prev reads
        if (i + 2 < NC) load_stage(i + 2, (i + 2) % 3);  // writes stage (i-1)%3: safe
        const uint32_t tb = sbase + (i % 3) * STAGE_BYTES;

        #pragma unroll
        for (int ks = 0; ks < 4; ks++) {
            uint32_t ah[4][4], al[4][4], bh[2][4], bl[2][4];
            #pragma unroll
            for (int mt = 0; mt < 4; mt++) {
                int row = wm + mt * 16 + (lane & 15);
                int kg  = ks * 2 + (lane >> 4);
                uint32_t off = row * 128 + ((kg ^ (row & 7)) << 4);
                LDSM4(ah[mt], tb + off);
                if (PASSES == 3) LDSM4(al[mt], tb + TILE_BYTES + off);
            }
            #pragma unroll
            for (int bt = 0; bt < 2; bt++) {
                int row = wn + bt * 16 + ((lane >> 4) << 3) + (lane & 7);
                int kg  = ks * 2 + ((lane >> 3) & 1);
                uint32_t off = row * 128 + ((kg ^ (row & 7)) << 4);
                LDSM4(bh[bt], tb + 2 * TILE_BYTES + off);
                LDSM4(bl[bt], tb + 3 * TILE_BYTES + off);
            }
            #pragma unroll
            for (int mt = 0; mt < 4; mt++)
                #pragma unroll
                for (int nt = 0; nt < 4; nt++)
                    MMA_BF16(acc[mt][nt], ah[mt],
                             bh[nt >> 1][(nt & 1) * 2], bh[nt >> 1][(nt & 1) * 2 + 1]);
            #pragma unroll
            for (int mt = 0; mt < 4; mt++)
                #pragma unroll
                for (int nt = 0; nt < 4; nt++)
                    MMA_BF16(acc[mt][nt], ah[mt],
                             bl[nt >> 1][(nt & 1) * 2], bl[nt >> 1][(nt & 1) * 2 + 1]);
            if (PASSES == 3) {
                #pragma unroll
                for (int mt = 0; mt < 4; mt++)
                    #pragma unroll
                    for (int nt = 0; nt < 4; nt++)
                        MMA_BF16(acc[mt][nt], al[mt],
                                 bh[nt >> 1][(nt & 1) * 2], bh[nt >> 1][(nt & 1) * 2 + 1]);
            }
        }
    }

    // ---- epilogue (fragment: rows g, g+8; cols 2t, 2t+1) ----
    const int g = lane >> 2, t = lane & 3;
    #pragma unroll
    for (int mt = 0; mt < 4; mt++) {
        #pragma unroll
        for (int nt = 0; nt < 4; nt++) {
            const int gr0 = m0 + wm + mt * 16 + g;
            const int gr1 = gr0 + 8;
            const int gc  = n0 + wn + nt * 8 + 2 * t;
            float v00 = acc[mt][nt][0], v01 = acc[mt][nt][1];
            float v10 = acc[mt][nt][2], v11 = acc[mt][nt][3];
            if (EPI == 3) {
                const float2 bv  = *(const float2*)&bias[gc];
                const float2 r0v = *(const float2*)&res[(size_t)gr0 * N + gc];
                const float2 r1v = *(const float2*)&res[(size_t)gr1 * N + gc];
                *(float2*)&Cf[(size_t)gr0 * N + gc] =
                    make_float2(v00 + bv.x + r0v.x, v01 + bv.y + r0v.y);
                *(float2*)&Cf[(size_t)gr1 * N + gc] =
                    make_float2(v10 + bv.x + r1v.x, v11 + bv.y + r1v.y);
            } else if (EPI == 2) {
                const float2 bv = *(const float2*)&bias[gc];
                float x00 = gelu_tanh(v00 + bv.x), x01 = gelu_tanh(v01 + bv.y);
                float x10 = gelu_tanh(v10 + bv.x), x11 = gelu_tanh(v11 + bv.y);
                __nv_bfloat162 h0, l0, h1, l1;
                split_hl(x00, h0.x, l0.x); split_hl(x01, h0.y, l0.y);
                split_hl(x10, h1.x, l1.x); split_hl(x11, h1.y, l1.y);
                *(__nv_bfloat162*)&Chi[(size_t)gr0 * N + gc] = h0;
                *(__nv_bfloat162*)&Clo[(size_t)gr0 * N + gc] = l0;
                *(__nv_bfloat162*)&Chi[(size_t)gr1 * N + gc] = h1;
                *(__nv_bfloat162*)&Clo[(size_t)gr1 * N + gc] = l1;
            } else { // EPI == 5: fused QKV
                const int seg = gc >> 10;       // constant per CTA
                const int col = gc & 1023;
                if (seg == 0) { v00 *= 0.125f; v01 *= 0.125f; v10 *= 0.125f; v11 *= 0.125f; }
                if (seg < 2) {
                    const size_t base = (size_t)seg * SEGSZ;
                    __nv_bfloat162 h0, l0, h1, l1;
                    split_hl(v00, h0.x, l0.x); split_hl(v01, h0.y, l0.y);
                    split_hl(v10, h1.x, l1.x); split_hl(v11, h1.y, l1.y);
                    *(__nv_bfloat162*)&Chi[base + (size_t)gr0 * DMODEL + col] = h0;
                    *(__nv_bfloat162*)&Clo[base + (size_t)gr0 * DMODEL + col] = l0;
                    *(__nv_bfloat162*)&Chi[base + (size_t)gr1 * DMODEL + col] = h1;
                    *(__nv_bfloat162*)&Clo[base + (size_t)gr1 * DMODEL + col] = l1;
                } else {    // V head-transposed: [b*16+h][d][s]
                    #pragma unroll
                    for (int e = 0; e < 4; e++) {
                        int gr = (e < 2) ? gr0 : gr1;
                        int cc = col + (e & 1);
                        float v = (e == 0) ? v00 : (e == 1) ? v01 : (e == 2) ? v10 : v11;
                        int b = gr >> 11, s = gr & 2047;
                        int h = cc >> 6, d = cc & 63;
                        size_t o = 2 * SEGSZ + ((size_t)((b * 16 + h) * 64 + d)) * 2048 + s;
                        bf16 hh, ll; split_hl(v, hh, ll);
                        Chi[o] = hh;
                        Clo[o] = ll;
                    }
                }
            }
        }
    }
}

// ---------------- mma.sync flash attention (bf16x2, causal) -> ctx hi/lo ----------
// CTA: 128 q-rows x one (b,h). 256 threads = 8 warps x 16 rows. KV tile = 64 keys.
// Q pre-scaled by 1/8. 2-pass compensation: S = Qh*Kh + Qh*Kl (Ql pass dropped);
// O += P*Vh + P*Vl with P rounded to bf16 (Pl pass dropped). Measured: +4.3e-5.
// smem: Qhi@0 (16KB); stage s @16384+s*32768: Khi,Klo,Vhi,Vlo (8KB each)
#define ATT_SMEM (16384 + 2*32768)

__global__ __launch_bounds__(256, 1)
void attn_mma(const bf16* __restrict__ qhi,
              const bf16* __restrict__ khi, const bf16* __restrict__ klo,
              const bf16* __restrict__ vthi, const bf16* __restrict__ vtlo,
              bf16* __restrict__ chi, bf16* __restrict__ clo)
{
    extern __shared__ char smem[];
    const uint32_t sbase = smem_u32(smem);
    const int tid  = threadIdx.x;
    const int wid  = tid >> 5, lane = tid & 31;
    const int g = lane >> 2, t = lane & 3;
    const int bh = blockIdx.y;
    const int b = bh >> 4, h = bh & 15;
    const int m0 = (gridDim.x - 1 - blockIdx.x) * 128;   // longest blocks first
    const int nit = m0 / 64 + 2;

    // ---- load Q tile (128 rows, hi only) ----
    {
        const bf16* qs = qhi + ((size_t)(b * SEQ + m0)) * DMODEL + h * 64;
        #pragma unroll
        for (int j = 0; j < 4; j++) {
            int cid = j * 256 + tid;
            int row = cid >> 3, c = cid & 7;
            cpa16(sbase + row * 128 + ((c ^ (row & 7)) << 4),
                  qs + (size_t)row * DMODEL + c * 8);
        }
        cpa_commit();
    }

    auto load_kv = [&](int it, int stage) {
        const int n0 = it * 64;
        const uint32_t base = sbase + 16384 + stage * 32768;
        const bf16* ks_[2] = { khi + ((size_t)(b * SEQ + n0)) * DMODEL + h * 64,
                               klo + ((size_t)(b * SEQ + n0)) * DMODEL + h * 64 };
        const bf16* vs_[2] = { vthi + ((size_t)(bh * 64)) * 2048 + n0,
                               vtlo + ((size_t)(bh * 64)) * 2048 + n0 };
        #pragma unroll
        for (int tl = 0; tl < 2; tl++)
            #pragma unroll
            for (int j = 0; j < 2; j++) {
                int cid = j * 256 + tid;
                int row = cid >> 3, c = cid & 7;
                uint32_t sw = row * 128 + ((c ^ (row & 7)) << 4);
                cpa16(base + tl * 8192 + sw,         ks_[tl] + (size_t)row * DMODEL + c * 8);
                cpa16(base + 16384 + tl * 8192 + sw, vs_[tl] + (size_t)row * 2048 + c * 8);
            }
        cpa_commit();
    };

    load_kv(0, 0);
    load_kv(1, 1);

    // Q fragments (constant across iters)
    cpa_wait2();
    __syncthreads();
    uint32_t qh[4][4];
    #pragma unroll
    for (int ks = 0; ks < 4; ks++) {
        int row = wid * 16 + (lane & 15);
        int kg  = ks * 2 + (lane >> 4);
        uint32_t off = row * 128 + ((kg ^ (row & 7)) << 4);
        LDSM4(qh[ks], sbase + off);
    }

    float m[2] = { -INFINITY, -INFINITY };
    float l[2] = { 0.f, 0.f };
    float acc_o[8][4];
    #pragma unroll
    for (int i = 0; i < 8; i++)
        #pragma unroll
        for (int c = 0; c < 4; c++) acc_o[i][c] = 0.f;

    const int rowL64 = (wid & 3) * 16 + g;
    const int wdiag  = (wid < 4) ? (nit - 2) : (nit - 1);

    for (int it = 0; it < nit; it++) {
        const int rem = nit - 1 - it;
        if (rem >= 1) cpa_wait1(); else cpa_wait0();
        __syncthreads();
        const uint32_t kb = sbase + 16384 + (it & 1) * 32768;
        const uint32_t vb = kb + 16384;
        const bool active = !(wid < 4 && it == nit - 1);

        if (active) {
            const bool diag = (it == wdiag);

            // ---- S = Q K^T (2-pass: Qh*Kh + Qh*Kl) ----
            float s[8][4];
            #pragma unroll
            for (int i = 0; i < 8; i++)
                #pragma unroll
                for (int c = 0; c < 4; c++) s[i][c] = 0.f;

            #pragma unroll
            for (int ks = 0; ks < 4; ks++) {
                uint32_t kh[4][4], kl[4][4];
                #pragma unroll
                for (int bt = 0; bt < 4; bt++) {
                    int row = bt * 16 + ((lane >> 4) << 3) + (lane & 7);
                    int kg  = ks * 2 + ((lane >> 3) & 1);
                    uint32_t off = row * 128 + ((kg ^ (row & 7)) << 4);
                    LDSM4(kh[bt], kb + off);
                    LDSM4(kl[bt], kb + 8192 + off);
                }
                #pragma unroll
                for (int nt = 0; nt < 8; nt++)
                    MMA_BF16(s[nt], qh[ks],
                             kh[nt >> 1][(nt & 1) * 2], kh[nt >> 1][(nt & 1) * 2 + 1]);
                #pragma unroll
                for (int nt = 0; nt < 8; nt++)
                    MMA_BF16(s[nt], qh[ks],
                             kl[nt >> 1][(nt & 1) * 2], kl[nt >> 1][(nt & 1) * 2 + 1]);
            }

            // ---- causal mask + online softmax (Q pre-scaled) ----
            #pragma unroll
            for (int nt = 0; nt < 8; nt++) {
                #pragma unroll
                for (int c = 0; c < 4; c++) {
                    int colL = nt * 8 + 2 * t + (c & 1);
                    int rowL = rowL64 + ((c >> 1) << 3);
                    if (diag && colL > rowL) s[nt][c] = -INFINITY;
                }
            }
            float mx0 = -INFINITY, mx1 = -INFINITY;
            #pragma unroll
            for (int nt = 0; nt < 8; nt++) {
                mx0 = fmaxf(mx0, fmaxf(s[nt][0], s[nt][1]));
                mx1 = fmaxf(mx1, fmaxf(s[nt][2], s[nt][3]));
            }
            mx0 = fmaxf(mx0, __shfl_xor_sync(0xFFFFFFFFu, mx0, 1));
            mx0 = fmaxf(mx0, __shfl_xor_sync(0xFFFFFFFFu, mx0, 2));
            mx1 = fmaxf(mx1, __shfl_xor_sync(0xFFFFFFFFu, mx1, 1));
            mx1 = fmaxf(mx1, __shfl_xor_sync(0xFFFFFFFFu, mx1, 2));
            float mn0 = fmaxf(m[0], mx0), mn1 = fmaxf(m[1], mx1);
            float a0 = __expf(m[0] - mn0), a1 = __expf(m[1] - mn1);
            m[0] = mn0; m[1] = mn1;
            #pragma unroll
            for (int i = 0; i < 8; i++) {
                acc_o[i][0] *= a0; acc_o[i][1] *= a0;
                acc_o[i][2] *= a1; acc_o[i][3] *= a1;
            }
            float sum0 = 0.f, sum1 = 0.f;
            float p[8][4];
            #pragma unroll
            for (int nt = 0; nt < 8; nt++) {
                p[nt][0] = __expf(s[nt][0] - mn0); p[nt][1] = __expf(s[nt][1] - mn0);
                p[nt][2] = __expf(s[nt][2] - mn1); p[nt][3] = __expf(s[nt][3] - mn1);
                sum0 += p[nt][0] + p[nt][1];
                sum1 += p[nt][2] + p[nt][3];
            }
            sum0 += __shfl_xor_sync(0xFFFFFFFFu, sum0, 1);
            sum0 += __shfl_xor_sync(0xFFFFFFFFu, sum0, 2);
            sum1 += __shfl_xor_sync(0xFFFFFFFFu, sum1, 1);
            sum1 += __shfl_xor_sync(0xFFFFFFFFu, sum1, 2);
            l[0] = l[0] * a0 + sum0;
            l[1] = l[1] * a1 + sum1;

            // ---- O += P V (2-pass: P*Vh + P*Vl; P rounded to bf16) ----
            #pragma unroll
            for (int ks2 = 0; ks2 < 4; ks2++) {
                uint32_t pah[4];
                #pragma unroll
                for (int e = 0; e < 2; e++) {
                    int nt = 2 * ks2 + e;
                    pah[e * 2 + 0] = pk2(p[nt][0], p[nt][1]);
                    pah[e * 2 + 1] = pk2(p[nt][2], p[nt][3]);
                }

                uint32_t vh[4][4], vl[4][4];
                #pragma unroll
                for (int dt = 0; dt < 4; dt++) {
                    int row = dt * 16 + ((lane >> 4) << 3) + (lane & 7);
                    int kg  = ks2 * 2 + ((lane >> 3) & 1);
                    uint32_t off = row * 128 + ((kg ^ (row & 7)) << 4);
                    LDSM4(vh[dt], vb + off);
                    LDSM4(vl[dt], vb + 8192 + off);
                }
                #pragma unroll
                for (int nt = 0; nt < 8; nt++)
                    MMA_BF16(acc_o[nt], pah,
                             vh[nt >> 1][(nt & 1) * 2], vh[nt >> 1][(nt & 1) * 2 + 1]);
                #pragma unroll
                for (int nt = 0; nt < 8; nt++)
                    MMA_BF16(acc_o[nt], pah,
                             vl[nt >> 1][(nt & 1) * 2], vl[nt >> 1][(nt & 1) * 2 + 1]);
            }
        }

        __syncthreads();
        if (it + 2 < nit) load_kv(it + 2, it & 1);
    }

    // ---- epilogue ----
    float inv0 = 1.0f / l[0], inv1 = 1.0f / l[1];
    const size_t gr0 = (size_t)(b * SEQ + m0 + wid * 16 + g) * DMODEL + h * 64;
    const size_t gr1 = gr0 + 8 * DMODEL;
    #pragma unroll
    for (int nt = 0; nt < 8; nt++) {
        int gc = nt * 8 + 2 * t;
        __nv_bfloat162 h0, l0h, h1, l1h;
        split_hl(acc_o[nt][0] * inv0, h0.x, l0h.x);
        split_hl(acc_o[nt][1] * inv0, h0.y, l0h.y);
        split_hl(acc_o[nt][2] * inv1, h1.x, l1h.x);
        split_hl(acc_o[nt][3] * inv1, h1.y, l1h.y);
        *(__nv_bfloat162*)&chi[gr0 + gc] = h0;
        *(__nv_bfloat162*)&clo[gr0 + gc] = l0h;
        *(__nv_bfloat162*)&chi[gr1 + gc] = h1;
        *(__nv_bfloat162*)&clo[gr1 + gc] = l1h;
    }
}

// ---------------- launch ----------------
extern "C" void kernel_launch(void* const* d_in, const int* in_sizes, int n_in,
                              void* d_out, int out_size)
{
    const float* x         = (const float*)d_in[0];
    const float* ln1_scale = (const float*)d_in[1];
    const float* ln1_shift = (const float*)d_in[2];
    const float* wq        = (const float*)d_in[3];
    const float* wk        = (const float*)d_in[4];
    const float* wv        = (const float*)d_in[5];
    const float* w_out     = (const float*)d_in[6];
    const float* b_out     = (const float*)d_in[7];
    const float* ln2_scale = (const float*)d_in[8];
    const float* ln2_shift = (const float*)d_in[9];
    const float* w1        = (const float*)d_in[10];
    const float* b1        = (const float*)d_in[11];
    const float* w2        = (const float*)d_in[12];
    const float* b2        = (const float*)d_in[13];
    float* out = (float*)d_out;

    float *p_res1;
    bf16 *p_ln1h, *p_ln1l, *p_qkvh, *p_qkvl;
    bf16 *p_ctxh, *p_ctxl, *p_ln2h, *p_ln2l, *p_h1h, *p_h1l;
    bf16 *p_wqkvh, *p_wqkvl, *p_woh, *p_wol, *p_w1h, *p_w1l, *p_w2h, *p_w2l;
    cudaGetSymbolAddress((void**)&p_res1,  g_res1);
    cudaGetSymbolAddress((void**)&p_ln1h,  g_ln1_hi);
    cudaGetSymbolAddress((void**)&p_ln1l,  g_ln1_lo);
    cudaGetSymbolAddress((void**)&p_qkvh,  g_qkv_hi);
    cudaGetSymbolAddress((void**)&p_qkvl,  g_qkv_lo);
    cudaGetSymbolAddress((void**)&p_ctxh,  g_ctx_hi);
    cudaGetSymbolAddress((void**)&p_ctxl,  g_ctx_lo);
    cudaGetSymbolAddress((void**)&p_ln2h,  g_ln2_hi);
    cudaGetSymbolAddress((void**)&p_ln2l,  g_ln2_lo);
    cudaGetSymbolAddress((void**)&p_h1h,   g_h1_hi);
    cudaGetSymbolAddress((void**)&p_h1l,   g_h1_lo);
    cudaGetSymbolAddress((void**)&p_wqkvh, g_wqkvT_hi);
    cudaGetSymbolAddress((void**)&p_wqkvl, g_wqkvT_lo);
    cudaGetSymbolAddress((void**)&p_woh,   g_woT_hi);
    cudaGetSymbolAddress((void**)&p_wol,   g_woT_lo);
    cudaGetSymbolAddress((void**)&p_w1h,   g_w1T_hi);
    cudaGetSymbolAddress((void**)&p_w1l,   g_w1T_lo);
    cudaGetSymbolAddress((void**)&p_w2h,   g_w2T_hi);
    cudaGetSymbolAddress((void**)&p_w2l,   g_w2T_lo);

    static bool attr_set = false;
    if (!attr_set) {
        cudaFuncSetAttribute(attn_mma,        cudaFuncAttributeMaxDynamicSharedMemorySize, ATT_SMEM);
        cudaFuncSetAttribute((gemm_mma<2,3>), cudaFuncAttributeMaxDynamicSharedMemorySize, GEMM_SMEM);
        cudaFuncSetAttribute((gemm_mma<3,3>), cudaFuncAttributeMaxDynamicSharedMemorySize, GEMM_SMEM);
        cudaFuncSetAttribute((gemm_mma<5,2>), cudaFuncAttributeMaxDynamicSharedMemorySize, GEMM_SMEM);
        attr_set = true;
    }

    // 0) weight transpose + hi/lo convert
    wconv_qkvo<<<dim3(DMODEL/32, DMODEL/32, 4), 256>>>(wq, wk, wv, w_out,
                                                       p_wqkvh, p_wqkvl, p_woh, p_wol);
    wconvT<<<dim3(FFN/32,    DMODEL/32), 256>>>(w1, p_w1h, p_w1l, DMODEL, FFN);
    wconvT<<<dim3(DMODEL/32, FFN/32),    256>>>(w2, p_w2h, p_w2l, FFN,    DMODEL);

    // 1) LN1 -> hi/lo
    ln_hl_kernel<<<MTOK, 256>>>(x, ln1_scale, ln1_shift, p_ln1h, p_ln1l);

    dim3 gQKV(3*DMODEL/128, MTOK/128);
    dim3 g1024(DMODEL/128,  MTOK/128);
    dim3 g4096(FFN/128,     MTOK/128);

    // 2) fused QKV projection (2-pass: softmax-damped error path)
    gemm_mma<5,2><<<gQKV, 256, GEMM_SMEM>>>(p_ln1h, p_ln1l, p_wqkvh, p_wqkvl,
                                            nullptr, nullptr, nullptr, p_qkvh, p_qkvl,
                                            MTOK, 3*DMODEL, DMODEL);

    // 3) attention (tensor core, 2-pass compensated) -> ctx hi/lo
    dim3 gAttn(SEQ/128, BATCH*NHEAD);
    attn_mma<<<gAttn, 256, ATT_SMEM>>>(p_qkvh,
                                       p_qkvh + SEGSZ,    p_qkvl + SEGSZ,
                                       p_qkvh + 2*SEGSZ,  p_qkvl + 2*SEGSZ,
                                       p_ctxh, p_ctxl);

    // 4) out projection (3-pass) + bias + residual(x) -> res1 (fp32)
    gemm_mma<3,3><<<g1024, 256, GEMM_SMEM>>>(p_ctxh, p_ctxl, p_woh, p_wol,
                                             b_out, x, p_res1, nullptr, nullptr,
                                             MTOK, DMODEL, DMODEL);

    // 5) LN2 -> hi/lo
    ln_hl_kernel<<<MTOK, 256>>>(p_res1, ln2_scale, ln2_shift, p_ln2h, p_ln2l);

    // 6) FFN1 (3-pass) + bias + gelu -> h1 hi/lo
    gemm_mma<2,3><<<g4096, 256, GEMM_SMEM>>>(p_ln2h, p_ln2l, p_w1h, p_w1l,
                                             b1, nullptr, nullptr, p_h1h, p_h1l,
                                             MTOK, FFN, DMODEL);

    // 7) FFN2 (3-pass) + bias + residual(res1) -> out
    gemm_mma<3,3><<<g1024, 256, GEMM_SMEM>>>(p_h1h, p_h1l, p_w2h, p_w2l,
                                             b2, p_res1, out, nullptr, nullptr,
                                             MTOK, DMODEL, FFN);

    (void)in_sizes; (void)n_in; (void)out_size;
}